// round 4
// baseline (speedup 1.0000x reference)
#include <cuda_runtime.h>
#include <math.h>

// Problem dims: B=4 O=4 L=128 N=8 V=256 H=256, Ls=2L=256, BO=16, BON=128, NL=1024

// ---------------- scratch (device globals; no allocation allowed) ----------------
__device__ float g_stmt_in[16 * 256 * 256];
__device__ float g_xg_stmt[16 * 256 * 768];
__device__ float g_stmt_h[16 * 256 * 256];
__device__ float g_xg_docs[128 * 128 * 768];
__device__ float g_docs_h[128 * 128 * 256];
__device__ float g_hs0[16 * 256], g_hs1[16 * 256];
__device__ float g_hd0[128 * 256], g_hd1[128 * 256];
__device__ float g_match[128 * 256 * 128];
__device__ float g_p1[128 * 256 * 128];
__device__ float g_p2t[128 * 128 * 256];
__device__ float g_read_sum[128 * 256 * 256];
__device__ float g_doc_read[128 * 128 * 256];
__device__ float g_dri[128 * 128 * 512];
__device__ float g_mm[16 * 1024 * 1024];
__device__ float g_att[128 * 128 * 512];
__device__ float g_xg_sr[128 * 256 * 768];
__device__ float g_xg_dr[128 * 128 * 768];
__device__ float g_hsr0[128 * 256], g_hsr1[128 * 256];
__device__ float g_hdr0[128 * 256], g_hdr1[128 * 256];
__device__ float g_srmax[128 * 256], g_drmax[128 * 256];

// ---------------- init: zero GRU states, -inf running maxes ----------------
__global__ void init_state() {
    int i = blockIdx.x * 256 + threadIdx.x;  // grid 128 -> 32768 threads
    if (i < 16 * 256) { g_hs0[i] = 0.f; g_hs1[i] = 0.f; }
    if (i < 128 * 256) {
        g_hd0[i] = 0.f;  g_hd1[i] = 0.f;
        g_hsr0[i] = 0.f; g_hsr1[i] = 0.f;
        g_hdr0[i] = 0.f; g_hdr1[i] = 0.f;
        g_srmax[i] = -1e30f; g_drmax[i] = -1e30f;
    }
}

// ---------------- build stmt = cat(question, answer) ----------------
__global__ void concat_stmt(const float* __restrict__ statement,
                            const float* __restrict__ answer) {
    int idx = blockIdx.x * 256 + threadIdx.x;  // grid 4096 -> 1048576
    int v = idx & 255;
    int s = (idx >> 8) & 255;
    int bo = idx >> 16;
    int b = bo >> 2;
    float val;
    if (s < 128) val = statement[(b * 128 + s) * 256 + v];
    else         val = answer[(bo * 128 + (s - 128)) * 256 + v];
    g_stmt_in[idx] = val;
}

// ---------------- dri = cat(docs, doc_read) ----------------
__global__ void concat_dri() {
    for (int idx = blockIdx.x * blockDim.x + threadIdx.x; idx < 128 * 128 * 512;
         idx += gridDim.x * blockDim.x) {
        int h = idx & 511;
        int rest = idx >> 9;  // bon*128 + l
        g_dri[idx] = (h < 256) ? g_docs_h[rest * 256 + h]
                               : g_doc_read[rest * 256 + (h - 256)];
    }
}

// ---------------- generic tiled SGEMM: C = A[M,K] * W[N,K]^T (+bias), batched ----------------
__global__ void __launch_bounds__(256) gemm_tn(
    const float* __restrict__ A, const float* __restrict__ W,
    const float* __restrict__ bias, float* __restrict__ C,
    int M, int N, int K, long long sA, long long sW, long long sC,
    int divA, int divW) {
    int z = blockIdx.z;
    A += (long long)(z / divA) * sA;
    W += (long long)(z / divW) * sW;
    C += (long long)z * sC;
    __shared__ float As[16][65];
    __shared__ float Ws[16][65];
    const int m0 = blockIdx.y * 64, n0 = blockIdx.x * 64;
    const int tid = threadIdx.x;
    const int tm = tid / 16, tn = tid % 16;
    const int lr = tid / 4;
    const int lk = (tid % 4) * 4;
    float acc[4][4];
#pragma unroll
    for (int i = 0; i < 4; i++)
#pragma unroll
        for (int j = 0; j < 4; j++) acc[i][j] = 0.f;

    for (int k0 = 0; k0 < K; k0 += 16) {
        float4 av = *reinterpret_cast<const float4*>(&A[(long long)(m0 + lr) * K + k0 + lk]);
        float4 wv = *reinterpret_cast<const float4*>(&W[(long long)(n0 + lr) * K + k0 + lk]);
        As[lk + 0][lr] = av.x; As[lk + 1][lr] = av.y; As[lk + 2][lr] = av.z; As[lk + 3][lr] = av.w;
        Ws[lk + 0][lr] = wv.x; Ws[lk + 1][lr] = wv.y; Ws[lk + 2][lr] = wv.z; Ws[lk + 3][lr] = wv.w;
        __syncthreads();
#pragma unroll
        for (int k = 0; k < 16; k++) {
            float a[4], b[4];
#pragma unroll
            for (int i = 0; i < 4; i++) a[i] = As[k][tm + 16 * i];
#pragma unroll
            for (int j = 0; j < 4; j++) b[j] = Ws[k][tn + 16 * j];
#pragma unroll
            for (int i = 0; i < 4; i++)
#pragma unroll
                for (int j = 0; j < 4; j++) acc[i][j] += a[i] * b[j];
        }
        __syncthreads();
    }
#pragma unroll
    for (int j = 0; j < 4; j++) {
        int n = n0 + tn + 16 * j;
        float bv = bias ? bias[n] : 0.f;
#pragma unroll
        for (int i = 0; i < 4; i++) {
            int m = m0 + tm + 16 * i;
            C[(long long)m * N + n] = acc[i][j] + bv;
        }
    }
}

// ---------------- generic tiled SGEMM: C = A[M,K] * B[K,N], batched ----------------
__global__ void __launch_bounds__(256) gemm_nn(
    const float* __restrict__ A, const float* __restrict__ Bm,
    float* __restrict__ C,
    int M, int N, int K, long long sA, long long sB, long long sC,
    int divA, int divB) {
    int z = blockIdx.z;
    A += (long long)(z / divA) * sA;
    Bm += (long long)(z / divB) * sB;
    C += (long long)z * sC;
    __shared__ float As[16][65];
    __shared__ float Bs[16][65];
    const int m0 = blockIdx.y * 64, n0 = blockIdx.x * 64;
    const int tid = threadIdx.x;
    const int tm = tid / 16, tn = tid % 16;
    const int lr = tid / 4;
    const int lk = (tid % 4) * 4;
    const int kb = tid / 16;
    const int nb = (tid % 16) * 4;
    float acc[4][4];
#pragma unroll
    for (int i = 0; i < 4; i++)
#pragma unroll
        for (int j = 0; j < 4; j++) acc[i][j] = 0.f;

    for (int k0 = 0; k0 < K; k0 += 16) {
        float4 av = *reinterpret_cast<const float4*>(&A[(long long)(m0 + lr) * K + k0 + lk]);
        float4 bv = *reinterpret_cast<const float4*>(&Bm[(long long)(k0 + kb) * N + n0 + nb]);
        As[lk + 0][lr] = av.x; As[lk + 1][lr] = av.y; As[lk + 2][lr] = av.z; As[lk + 3][lr] = av.w;
        Bs[kb][nb + 0] = bv.x; Bs[kb][nb + 1] = bv.y; Bs[kb][nb + 2] = bv.z; Bs[kb][nb + 3] = bv.w;
        __syncthreads();
#pragma unroll
        for (int k = 0; k < 16; k++) {
            float a[4], b[4];
#pragma unroll
            for (int i = 0; i < 4; i++) a[i] = As[k][tm + 16 * i];
#pragma unroll
            for (int j = 0; j < 4; j++) b[j] = Bs[k][tn + 16 * j];
#pragma unroll
            for (int i = 0; i < 4; i++)
#pragma unroll
                for (int j = 0; j < 4; j++) acc[i][j] += a[i] * b[j];
        }
        __syncthreads();
    }
#pragma unroll
    for (int j = 0; j < 4; j++) {
        int n = n0 + tn + 16 * j;
#pragma unroll
        for (int i = 0; i < 4; i++) {
            int m = m0 + tm + 16 * i;
            C[(long long)m * N + n] = acc[i][j];
        }
    }
}

// ---------------- row softmax (in can equal out) ----------------
__global__ void softmax_rows(const float* __restrict__ in, float* __restrict__ out, int cols) {
    int row = blockIdx.x;
    const float* x = in + (long long)row * cols;
    float* y = out + (long long)row * cols;
    __shared__ float red[256];
    int tid = threadIdx.x;
    float m = -1e30f;
    for (int c = tid; c < cols; c += 256) m = fmaxf(m, x[c]);
    red[tid] = m; __syncthreads();
    for (int s = 128; s > 0; s >>= 1) {
        if (tid < s) red[tid] = fmaxf(red[tid], red[tid + s]);
        __syncthreads();
    }
    m = red[0]; __syncthreads();
    float sum = 0.f;
    for (int c = tid; c < cols; c += 256) sum += expf(x[c] - m);
    red[tid] = sum; __syncthreads();
    for (int s = 128; s > 0; s >>= 1) {
        if (tid < s) red[tid] += red[tid + s];
        __syncthreads();
    }
    float inv = 1.f / red[0];
    for (int c = tid; c < cols; c += 256) y[c] = expf(x[c] - m) * inv;
}

// ---------------- column softmax of match over s, output transposed [bon][l][s] ----------------
__global__ void __launch_bounds__(128) softmax_cols_t() {
    int bon = blockIdx.y;
    int l = blockIdx.x * 4 + (threadIdx.x >> 5);
    int lane = threadIdx.x & 31;
    const float* base = g_match + (long long)bon * 256 * 128 + l;
    float v[8];
    float m = -1e30f;
#pragma unroll
    for (int i = 0; i < 8; i++) {
        v[i] = base[(lane + 32 * i) * 128];
        m = fmaxf(m, v[i]);
    }
#pragma unroll
    for (int off = 16; off; off >>= 1) m = fmaxf(m, __shfl_xor_sync(0xffffffffu, m, off));
    float sum = 0.f;
#pragma unroll
    for (int i = 0; i < 8; i++) { v[i] = expf(v[i] - m); sum += v[i]; }
#pragma unroll
    for (int off = 16; off; off >>= 1) sum += __shfl_xor_sync(0xffffffffu, sum, off);
    float inv = 1.f / sum;
    float* o = g_p2t + ((long long)bon * 128 + l) * 256;
#pragma unroll
    for (int i = 0; i < 8; i++) o[lane + 32 * i] = v[i] * inv;
}

// ---------------- fused GRU step: hg = h@Whh^T + bhh; gates; h update ----------------
struct GruGroup {
    const float* xg;    // [nseq][T][768]
    const float* whh;   // [768][256]
    const float* bhh;   // [768]
    const float* hin;   // [nseq][256]
    float* hout;        // [nseq][256]
    float* ys;          // optional [nseq][T][256]
    float* hmax;        // optional [nseq][256]
    int T;
};

// grid: (16 colchunks, chunks0 + chunks1); block 128; tile 16 seqs x 16 cols
__global__ void __launch_bounds__(128) gru_step(GruGroup g0, GruGroup g1, int chunks0, int t) {
    GruGroup g;
    int s0;
    if ((int)blockIdx.y < chunks0) { g = g0; s0 = blockIdx.y * 16; }
    else                           { g = g1; s0 = (blockIdx.y - chunks0) * 16; }
    const int colbase = blockIdx.x * 16;
    const int tid = threadIdx.x;
    const int ci = tid & 15;
    const int sj = tid >> 4;  // 0..7

    __shared__ __align__(16) float hs[16][256];
    __shared__ float ws[48][65];

    // stage h tile [16][256]
    for (int i = tid; i < 1024; i += 128) {
        int s = i >> 6;
        int k4 = i & 63;
        float4 v = *reinterpret_cast<const float4*>(&g.hin[(long long)(s0 + s) * 256 + k4 * 4]);
        *reinterpret_cast<float4*>(&hs[s][k4 * 4]) = v;
    }

    float ar0 = 0.f, az0 = 0.f, an0 = 0.f, ar1 = 0.f, az1 = 0.f, an1 = 0.f;
    for (int kc = 0; kc < 4; kc++) {
        __syncthreads();
        // stage whh rows {i, 256+i, 512+i : i in coltile} for k chunk kc
        for (int i = tid; i < 768; i += 128) {
            int r = i >> 4;       // 0..47
            int k4 = i & 15;
            int gidx = r >> 4;    // gate 0..2
            int j = r & 15;       // col within chunk
            int row = gidx * 256 + colbase + j;
            float4 v = *reinterpret_cast<const float4*>(&g.whh[(long long)row * 256 + kc * 64 + k4 * 4]);
            ws[r][k4 * 4 + 0] = v.x; ws[r][k4 * 4 + 1] = v.y;
            ws[r][k4 * 4 + 2] = v.z; ws[r][k4 * 4 + 3] = v.w;
        }
        __syncthreads();
#pragma unroll 16
        for (int k = 0; k < 64; k++) {
            float wr = ws[ci][k], wz = ws[16 + ci][k], wn = ws[32 + ci][k];
            float h0 = hs[sj][kc * 64 + k];
            float h1 = hs[sj + 8][kc * 64 + k];
            ar0 += wr * h0; az0 += wz * h0; an0 += wn * h0;
            ar1 += wr * h1; az1 += wz * h1; an1 += wn * h1;
        }
    }

    const int i = colbase + ci;
    const float br = g.bhh[i], bz = g.bhh[256 + i], bn = g.bhh[512 + i];
#pragma unroll
    for (int p = 0; p < 2; p++) {
        int sl = sj + 8 * p;
        int seq = s0 + sl;
        const float* xrow = g.xg + ((long long)seq * g.T + t) * 768;
        float hr = (p ? ar1 : ar0) + br;
        float hz = (p ? az1 : az0) + bz;
        float hn = (p ? an1 : an0) + bn;
        float r = 1.f / (1.f + expf(-(xrow[i] + hr)));
        float z = 1.f / (1.f + expf(-(xrow[256 + i] + hz)));
        float n = tanhf(xrow[512 + i] + r * hn);
        float hold = hs[sl][i];
        float h = (1.f - z) * n + z * hold;
        g.hout[(long long)seq * 256 + i] = h;
        if (g.ys) g.ys[((long long)seq * g.T + t) * 256 + i] = h;
        if (g.hmax) {
            float* mp = &g.hmax[(long long)seq * 256 + i];
            *mp = fmaxf(*mp, h);
        }
    }
}

// ---------------- final: coef gate, feat, output head, softmax over options ----------------
__global__ void __launch_bounds__(512) final_kernel(
    const float* __restrict__ gate_w, const float* __restrict__ gate_b,
    const float* __restrict__ out_w, const float* __restrict__ out_b,
    float* __restrict__ out) {
    __shared__ float coef[128];
    __shared__ float logits[16];
    int tid = threadIdx.x, w = tid >> 5, lane = tid & 31;
    // coef[bon] = res . gate_w + gate_b   (no sigmoid)
    for (int bon = w; bon < 128; bon += 16) {
        float s = 0.f;
        for (int d = lane; d < 512; d += 32) {
            float rv = (d < 256) ? g_srmax[bon * 256 + d] : g_drmax[bon * 256 + d - 256];
            s += rv * gate_w[d];
        }
#pragma unroll
        for (int off = 16; off; off >>= 1) s += __shfl_xor_sync(0xffffffffu, s, off);
        if (lane == 0) coef[bon] = s + gate_b[0];
    }
    __syncthreads();
    // logits[bo] = feat . out_w + out_b, feat = [max_n(coef*res), mean_n(coef*res)]
    {
        int bo = w;
        float acc = 0.f;
        for (int d = lane; d < 1024; d += 32) {
            float v;
            if (d < 512) {
                float mx = -1e30f;
#pragma unroll
                for (int n = 0; n < 8; n++) {
                    int bon = bo * 8 + n;
                    float rv = (d < 256) ? g_srmax[bon * 256 + d] : g_drmax[bon * 256 + d - 256];
                    mx = fmaxf(mx, coef[bon] * rv);
                }
                v = mx;
            } else {
                int dd = d - 512;
                float sm = 0.f;
#pragma unroll
                for (int n = 0; n < 8; n++) {
                    int bon = bo * 8 + n;
                    float rv = (dd < 256) ? g_srmax[bon * 256 + dd] : g_drmax[bon * 256 + dd - 256];
                    sm += coef[bon] * rv;
                }
                v = sm * 0.125f;
            }
            acc += v * out_w[d];
        }
#pragma unroll
        for (int off = 16; off; off >>= 1) acc += __shfl_xor_sync(0xffffffffu, acc, off);
        if (lane == 0) logits[bo] = acc + out_b[0];
    }
    __syncthreads();
    if (tid < 4) {
        int b = tid;
        float m = -1e30f;
        for (int o = 0; o < 4; o++) m = fmaxf(m, logits[b * 4 + o]);
        float e[4], s = 0.f;
        for (int o = 0; o < 4; o++) { e[o] = expf(logits[b * 4 + o] - m); s += e[o]; }
        for (int o = 0; o < 4; o++) out[b * 4 + o] = e[o] / s;
    }
}

// ---------------- host orchestration ----------------
#define SYM(p, s) do { void* _t = nullptr; cudaGetSymbolAddress(&_t, s); p = (float*)_t; } while (0)

extern "C" void kernel_launch(void* const* d_in, const int* in_sizes, int n_in,
                              void* d_out, int out_size) {
    const float* statement = (const float*)d_in[0];
    const float* answer    = (const float*)d_in[1];
    const float* refs      = (const float*)d_in[2];
    const float* ctx_wih   = (const float*)d_in[3];
    const float* ctx_whh   = (const float*)d_in[4];
    const float* ctx_bih   = (const float*)d_in[5];
    const float* ctx_bhh   = (const float*)d_in[6];
    const float* sr_wih    = (const float*)d_in[7];
    const float* sr_whh    = (const float*)d_in[8];
    const float* sr_bih    = (const float*)d_in[9];
    const float* sr_bhh    = (const float*)d_in[10];
    const float* dr_wih    = (const float*)d_in[11];
    const float* dr_whh    = (const float*)d_in[12];
    const float* dr_bih    = (const float*)d_in[13];
    const float* dr_bhh    = (const float*)d_in[14];
    const float* gate_w    = (const float*)d_in[15];
    const float* gate_b    = (const float*)d_in[16];
    const float* out_w     = (const float*)d_in[17];
    const float* out_b     = (const float*)d_in[18];
    float* out = (float*)d_out;

    float *stmt_in, *xg_stmt, *stmt_h, *xg_docs, *docs_h;
    float *hs0, *hs1, *hd0, *hd1;
    float *matchb, *p1, *p2t, *read_sum, *doc_read, *dri, *mmb, *att;
    float *xg_sr, *xg_dr, *hsr0, *hsr1, *hdr0, *hdr1, *srmax, *drmax;
    SYM(stmt_in, g_stmt_in); SYM(xg_stmt, g_xg_stmt); SYM(stmt_h, g_stmt_h);
    SYM(xg_docs, g_xg_docs); SYM(docs_h, g_docs_h);
    SYM(hs0, g_hs0); SYM(hs1, g_hs1); SYM(hd0, g_hd0); SYM(hd1, g_hd1);
    SYM(matchb, g_match); SYM(p1, g_p1); SYM(p2t, g_p2t);
    SYM(read_sum, g_read_sum); SYM(doc_read, g_doc_read); SYM(dri, g_dri);
    SYM(mmb, g_mm); SYM(att, g_att);
    SYM(xg_sr, g_xg_sr); SYM(xg_dr, g_xg_dr);
    SYM(hsr0, g_hsr0); SYM(hsr1, g_hsr1); SYM(hdr0, g_hdr0); SYM(hdr1, g_hdr1);
    SYM(srmax, g_srmax); SYM(drmax, g_drmax);

    init_state<<<128, 256>>>();
    concat_stmt<<<4096, 256>>>(statement, answer);

    // input projections for ctx GRU
    gemm_tn<<<dim3(12, 64, 1), 256>>>(stmt_in, ctx_wih, ctx_bih, xg_stmt,
                                      4096, 768, 256, 0, 0, 0, 1, 1);
    gemm_tn<<<dim3(12, 256, 1), 256>>>(refs, ctx_wih, ctx_bih, xg_docs,
                                       16384, 768, 256, 0, 0, 0, 1, 1);

    // phase A: ctx GRU over stmt (16 seqs, 256 steps) || docs (128 seqs, 128 steps)
    for (int t = 0; t < 256; t++) {
        GruGroup gs;
        gs.xg = xg_stmt; gs.whh = ctx_whh; gs.bhh = ctx_bhh;
        gs.hin = (t & 1) ? hs1 : hs0; gs.hout = (t & 1) ? hs0 : hs1;
        gs.ys = stmt_h; gs.hmax = nullptr; gs.T = 256;
        GruGroup gd;
        gd.xg = xg_docs; gd.whh = ctx_whh; gd.bhh = ctx_bhh;
        gd.hin = (t & 1) ? hd1 : hd0; gd.hout = (t & 1) ? hd0 : hd1;
        gd.ys = docs_h; gd.hmax = nullptr; gd.T = 128;
        int chunks = 1 + ((t < 128) ? 8 : 0);
        gru_step<<<dim3(16, chunks), 128>>>(gs, gd, 1, t);
    }

    // match[bon][s][l] = stmt[bo,s,:] . docs[bon,l,:]
    gemm_tn<<<dim3(2, 4, 128), 256>>>(stmt_h, docs_h, nullptr, matchb,
                                      256, 128, 256, 65536, 32768, 32768, 8, 1);
    // softmax over l -> p1 ; softmax over s (transposed out) -> p2t
    softmax_rows<<<32768, 256>>>(matchb, p1, 128);
    softmax_cols_t<<<dim3(32, 128), 128>>>();
    // read_sum = p1 @ docs ; doc_read = p2t @ stmt
    gemm_nn<<<dim3(4, 4, 128), 256>>>(p1, docs_h, read_sum,
                                      256, 256, 128, 32768, 32768, 65536, 1, 1);
    gemm_nn<<<dim3(4, 2, 128), 256>>>(p2t, stmt_h, doc_read,
                                      128, 256, 256, 32768, 65536, 32768, 1, 8);
    concat_dri<<<4096, 256>>>();

    // doc-doc cross attention per bo: mm = dri @ dri^T ; softmax ; att = p3 @ dri
    gemm_tn<<<dim3(16, 16, 16), 256>>>(dri, dri, nullptr, mmb,
                                       1024, 1024, 512, 524288, 524288, 1048576, 1, 1);
    softmax_rows<<<16384, 256>>>(mmb, mmb, 1024);
    gemm_nn<<<dim3(8, 16, 16), 256>>>(mmb, dri, att,
                                      1024, 512, 1024, 1048576, 524288, 524288, 1, 1);

    // input projections for reasoning GRUs
    gemm_tn<<<dim3(12, 512, 1), 256>>>(read_sum, sr_wih, sr_bih, xg_sr,
                                       32768, 768, 256, 0, 0, 0, 1, 1);
    gemm_tn<<<dim3(12, 256, 1), 256>>>(att, dr_wih, dr_bih, xg_dr,
                                       16384, 768, 512, 0, 0, 0, 1, 1);

    // phase C: sr GRU (128 seqs, 256 steps) || dr GRU (128 seqs, 128 steps); running max over t
    for (int t = 0; t < 256; t++) {
        GruGroup ga;
        ga.xg = xg_sr; ga.whh = sr_whh; ga.bhh = sr_bhh;
        ga.hin = (t & 1) ? hsr1 : hsr0; ga.hout = (t & 1) ? hsr0 : hsr1;
        ga.ys = nullptr; ga.hmax = srmax; ga.T = 256;
        GruGroup gb;
        gb.xg = xg_dr; gb.whh = dr_whh; gb.bhh = dr_bhh;
        gb.hin = (t & 1) ? hdr1 : hdr0; gb.hout = (t & 1) ? hdr0 : hdr1;
        gb.ys = nullptr; gb.hmax = drmax; gb.T = 128;
        int chunks = 8 + ((t < 128) ? 8 : 0);
        gru_step<<<dim3(16, chunks), 128>>>(ga, gb, 8, t);
    }

    final_kernel<<<1, 512>>>(gate_w, gate_b, out_w, out_b, out);
}

// round 5
// speedup vs baseline: 1.3202x; 1.3202x over previous
#include <cuda_runtime.h>
#include <math.h>

// Problem dims: B=4 O=4 L=128 N=8 V=256 H=256, Ls=2L=256, BO=16, BON=128, NL=1024

// ---------------- scratch (device globals; no allocation allowed) ----------------
__device__ float g_stmt_in[16 * 256 * 256];
__device__ float g_xg_stmt[16 * 256 * 768];
__device__ float g_stmt_h[16 * 256 * 256];
__device__ float g_xg_docs[128 * 128 * 768];
__device__ float g_docs_h[128 * 128 * 256];
__device__ float g_hs0[16 * 256], g_hs1[16 * 256];
__device__ float g_hd0[128 * 256], g_hd1[128 * 256];
__device__ float g_match[128 * 256 * 128];
__device__ float g_p1[128 * 256 * 128];
__device__ float g_p2t[128 * 128 * 256];
__device__ float g_read_sum[128 * 256 * 256];
__device__ float g_doc_read[128 * 128 * 256];
__device__ float g_dri[128 * 128 * 512];
__device__ float g_mm[16 * 1024 * 1024];
__device__ float g_att[128 * 128 * 512];
__device__ float g_xg_sr[128 * 256 * 768];
__device__ float g_xg_dr[128 * 128 * 768];
__device__ float g_hsr0[128 * 256], g_hsr1[128 * 256];
__device__ float g_hdr0[128 * 256], g_hdr1[128 * 256];
__device__ float g_srmax[128 * 256], g_drmax[128 * 256];

__device__ unsigned int g_bar_count;
__device__ unsigned int g_bar_gen;

// ---------------- init ----------------
__global__ void init_state() {
    int i = blockIdx.x * 256 + threadIdx.x;  // 32768 threads
    if (i == 0) { g_bar_count = 0; g_bar_gen = 0; }
    if (i < 16 * 256) { g_hs0[i] = 0.f; g_hs1[i] = 0.f; }
    if (i < 128 * 256) {
        g_hd0[i] = 0.f;  g_hd1[i] = 0.f;
        g_hsr0[i] = 0.f; g_hsr1[i] = 0.f;
        g_hdr0[i] = 0.f; g_hdr1[i] = 0.f;
    }
}

// ---------------- build stmt = cat(question, answer) ----------------
__global__ void concat_stmt(const float* __restrict__ statement,
                            const float* __restrict__ answer) {
    int idx = blockIdx.x * 256 + threadIdx.x;  // 1048576
    int v = idx & 255;
    int s = (idx >> 8) & 255;
    int bo = idx >> 16;
    int b = bo >> 2;
    float val;
    if (s < 128) val = statement[(b * 128 + s) * 256 + v];
    else         val = answer[(bo * 128 + (s - 128)) * 256 + v];
    g_stmt_in[idx] = val;
}

// ---------------- dri = cat(docs, doc_read) ----------------
__global__ void concat_dri() {
    for (int idx = blockIdx.x * blockDim.x + threadIdx.x; idx < 128 * 128 * 512;
         idx += gridDim.x * blockDim.x) {
        int h = idx & 511;
        int rest = idx >> 9;
        g_dri[idx] = (h < 256) ? g_docs_h[rest * 256 + h]
                               : g_doc_read[rest * 256 + (h - 256)];
    }
}

// ---------------- 128x128x16 SGEMM, 8x8 per thread ----------------
// TB=1: C = A[M,K] * B[N,K]^T (+bias);  TB=0: C = A[M,K] * B[K,N]
template <int TB>
__global__ void __launch_bounds__(256) gemm128(
    const float* __restrict__ A, const float* __restrict__ B,
    const float* __restrict__ bias, float* __restrict__ C,
    int M, int N, int K, long long sA, long long sB, long long sC,
    int divA, int divB) {
    int z = blockIdx.z;
    A += (long long)(z / divA) * sA;
    B += (long long)(z / divB) * sB;
    C += (long long)z * sC;
    __shared__ float As[16][132];
    __shared__ float Bs[16][132];
    const int m0 = blockIdx.y * 128, n0 = blockIdx.x * 128;
    const int tid = threadIdx.x;
    const int tx = tid & 15, ty = tid >> 4;
    const int lr = tid >> 2;          // 0..63
    const int lk = (tid & 3) * 4;
    const int kb = tid >> 5;          // 0..7
    const int nb = (tid & 31) * 4;

    float acc[8][8];
#pragma unroll
    for (int i = 0; i < 8; i++)
#pragma unroll
        for (int j = 0; j < 8; j++) acc[i][j] = 0.f;

    for (int k0 = 0; k0 < K; k0 += 16) {
#pragma unroll
        for (int h = 0; h < 2; h++) {
            int r = lr + h * 64;
            float4 v = *reinterpret_cast<const float4*>(&A[(long long)(m0 + r) * K + k0 + lk]);
            As[lk + 0][r] = v.x; As[lk + 1][r] = v.y; As[lk + 2][r] = v.z; As[lk + 3][r] = v.w;
        }
        if (TB) {
#pragma unroll
            for (int h = 0; h < 2; h++) {
                int r = lr + h * 64;
                float4 v = *reinterpret_cast<const float4*>(&B[(long long)(n0 + r) * K + k0 + lk]);
                Bs[lk + 0][r] = v.x; Bs[lk + 1][r] = v.y; Bs[lk + 2][r] = v.z; Bs[lk + 3][r] = v.w;
            }
        } else {
#pragma unroll
            for (int h = 0; h < 2; h++) {
                int r = kb + h * 8;
                float4 v = *reinterpret_cast<const float4*>(&B[(long long)(k0 + r) * N + n0 + nb]);
                *reinterpret_cast<float4*>(&Bs[r][nb]) = v;
            }
        }
        __syncthreads();
#pragma unroll
        for (int kk = 0; kk < 16; kk++) {
            float4 a0 = *reinterpret_cast<const float4*>(&As[kk][ty * 8]);
            float4 a1 = *reinterpret_cast<const float4*>(&As[kk][ty * 8 + 4]);
            float4 b0 = *reinterpret_cast<const float4*>(&Bs[kk][tx * 8]);
            float4 b1 = *reinterpret_cast<const float4*>(&Bs[kk][tx * 8 + 4]);
            float a[8] = {a0.x, a0.y, a0.z, a0.w, a1.x, a1.y, a1.z, a1.w};
            float b[8] = {b0.x, b0.y, b0.z, b0.w, b1.x, b1.y, b1.z, b1.w};
#pragma unroll
            for (int i = 0; i < 8; i++)
#pragma unroll
                for (int j = 0; j < 8; j++) acc[i][j] += a[i] * b[j];
        }
        __syncthreads();
    }
#pragma unroll
    for (int i = 0; i < 8; i++) {
        int m = m0 + ty * 8 + i;
#pragma unroll
        for (int jj = 0; jj < 2; jj++) {
            int n = n0 + tx * 8 + jj * 4;
            float4 v;
            v.x = acc[i][jj * 4 + 0]; v.y = acc[i][jj * 4 + 1];
            v.z = acc[i][jj * 4 + 2]; v.w = acc[i][jj * 4 + 3];
            if (bias) {
                v.x += bias[n + 0]; v.y += bias[n + 1];
                v.z += bias[n + 2]; v.w += bias[n + 3];
            }
            *reinterpret_cast<float4*>(&C[(long long)m * N + n]) = v;
        }
    }
}

// ---------------- row softmax (in can equal out) ----------------
__global__ void softmax_rows(const float* __restrict__ in, float* __restrict__ out, int cols) {
    int row = blockIdx.x;
    const float* x = in + (long long)row * cols;
    float* y = out + (long long)row * cols;
    __shared__ float red[256];
    int tid = threadIdx.x;
    float m = -1e30f;
    for (int c = tid; c < cols; c += 256) m = fmaxf(m, x[c]);
    red[tid] = m; __syncthreads();
    for (int s = 128; s > 0; s >>= 1) {
        if (tid < s) red[tid] = fmaxf(red[tid], red[tid + s]);
        __syncthreads();
    }
    m = red[0]; __syncthreads();
    float sum = 0.f;
    for (int c = tid; c < cols; c += 256) sum += expf(x[c] - m);
    red[tid] = sum; __syncthreads();
    for (int s = 128; s > 0; s >>= 1) {
        if (tid < s) red[tid] += red[tid + s];
        __syncthreads();
    }
    float inv = 1.f / red[0];
    for (int c = tid; c < cols; c += 256) y[c] = expf(x[c] - m) * inv;
}

// ---------------- column softmax of match over s, output transposed [bon][l][s] ----------------
__global__ void __launch_bounds__(128) softmax_cols_t() {
    int bon = blockIdx.y;
    int l = blockIdx.x * 4 + (threadIdx.x >> 5);
    int lane = threadIdx.x & 31;
    const float* base = g_match + (long long)bon * 256 * 128 + l;
    float v[8];
    float m = -1e30f;
#pragma unroll
    for (int i = 0; i < 8; i++) {
        v[i] = base[(lane + 32 * i) * 128];
        m = fmaxf(m, v[i]);
    }
#pragma unroll
    for (int off = 16; off; off >>= 1) m = fmaxf(m, __shfl_xor_sync(0xffffffffu, m, off));
    float sum = 0.f;
#pragma unroll
    for (int i = 0; i < 8; i++) { v[i] = expf(v[i] - m); sum += v[i]; }
#pragma unroll
    for (int off = 16; off; off >>= 1) sum += __shfl_xor_sync(0xffffffffu, sum, off);
    float inv = 1.f / sum;
    float* o = g_p2t + ((long long)bon * 128 + l) * 256;
#pragma unroll
    for (int i = 0; i < 8; i++) o[lane + 32 * i] = v[i] * inv;
}

// ---------------- grid barrier (all blocks resident by construction) ----------------
__device__ __forceinline__ void grid_barrier(unsigned nblocks) {
    __syncthreads();
    if (threadIdx.x == 0) {
        volatile unsigned* genp = &g_bar_gen;
        unsigned gen = *genp;
        __threadfence();
        unsigned old = atomicAdd(&g_bar_count, 1u);
        if (old == nblocks - 1) {
            *((volatile unsigned*)&g_bar_count) = 0;
            __threadfence();
            *genp = gen + 1;
        } else {
            while (*genp == gen) { __nanosleep(32); }
        }
    }
    __syncthreads();
}

// ---------------- persistent fused GRU phase ----------------
struct GG {
    const float* xg;    // [nseq][T][768]
    const float* whh;   // [768][256]
    const float* bhh;   // [768]
    float* h0;          // [nseq][256] (t even input)
    float* h1;
    float* ys;          // optional [nseq][T][256]
    float* hmax;        // optional [nseq][256]
    int T;
    int nsg;            // seq groups of 16
};

#define WP 260  // padded weight row pitch (floats)
#define DOT4(w, h) ((w).x * (h).x + (w).y * (h).y + (w).z * (h).z + (w).w * (h).w)

// block = 128 threads, tile = 16 seqs x 32 cols. grid = (ga.nsg + gb.nsg) * 8 blocks.
__global__ void __launch_bounds__(128) gru_phase(GG ga, GG gb) {
    extern __shared__ float sm[];
    float* ws = sm;               // 96 x WP
    float* hs = sm + 96 * WP;     // 16 x 256

    GG g;
    int sgrp, colbase;
    {
        int b = blockIdx.x;
        int blocks0 = ga.nsg * 8;
        if (b < blocks0) { g = ga; sgrp = b >> 3; colbase = (b & 7) * 32; }
        else { g = gb; int bb = b - blocks0; sgrp = bb >> 3; colbase = (bb & 7) * 32; }
    }
    const int tid = threadIdx.x;
    const int ci = tid & 15;
    const int sj = tid >> 4;  // 0..7
    const unsigned nblocks = gridDim.x;

    // load weight slice: rows {gate*256 + colbase + j}, j in [0,32), all 256 k
    for (int i = tid; i < 96 * 64; i += 128) {
        int r = i >> 6, q = i & 63;
        float4 v = __ldg(reinterpret_cast<const float4*>(
            &g.whh[(long long)((r >> 5) * 256 + colbase + (r & 31)) * 256 + q * 4]));
        *reinterpret_cast<float4*>(&ws[r * WP + q * 4]) = v;
    }
    const int c0 = colbase + ci, c1 = c0 + 16;
    const float br0 = g.bhh[c0], bz0 = g.bhh[256 + c0], bn0 = g.bhh[512 + c0];
    const float br1 = g.bhh[c1], bz1 = g.bhh[256 + c1], bn1 = g.bhh[512 + c1];
    float mx00 = -1e30f, mx01 = -1e30f, mx10 = -1e30f, mx11 = -1e30f;

    const float4* pr0 = reinterpret_cast<const float4*>(&ws[(0 * 32 + ci) * WP]);
    const float4* pr1 = reinterpret_cast<const float4*>(&ws[(0 * 32 + ci + 16) * WP]);
    const float4* pz0 = reinterpret_cast<const float4*>(&ws[(1 * 32 + ci) * WP]);
    const float4* pz1 = reinterpret_cast<const float4*>(&ws[(1 * 32 + ci + 16) * WP]);
    const float4* pn0 = reinterpret_cast<const float4*>(&ws[(2 * 32 + ci) * WP]);
    const float4* pn1 = reinterpret_cast<const float4*>(&ws[(2 * 32 + ci + 16) * WP]);
    const float4* h0p = reinterpret_cast<const float4*>(&hs[sj * 256]);
    const float4* h1p = reinterpret_cast<const float4*>(&hs[(sj + 8) * 256]);

    for (int t = 0; t < 256; t++) {
        if (t < g.T) {
            const float* hin = (t & 1) ? g.h1 : g.h0;
            float* hout = (t & 1) ? g.h0 : g.h1;
            const float* tilebase = hin + (long long)sgrp * 16 * 256;
            // stage h tile [16][256] (L2-only loads: written by other SMs last step)
#pragma unroll
            for (int i = 0; i < 8; i++) {
                int idx = tid + i * 128;  // 0..1023 float4
                float4 v = __ldcg(reinterpret_cast<const float4*>(tilebase) + idx);
                *reinterpret_cast<float4*>(&hs[idx * 4]) = v;
            }
            // prefetch xg for this thread's 4 cells (overlaps with compute)
            const long long base0 = ((long long)(sgrp * 16 + sj) * g.T + t) * 768;
            const long long base1 = ((long long)(sgrp * 16 + sj + 8) * g.T + t) * 768;
            float xr00 = __ldg(&g.xg[base0 + c0]);
            float xz00 = __ldg(&g.xg[base0 + 256 + c0]);
            float xn00 = __ldg(&g.xg[base0 + 512 + c0]);
            float xr01 = __ldg(&g.xg[base0 + c1]);
            float xz01 = __ldg(&g.xg[base0 + 256 + c1]);
            float xn01 = __ldg(&g.xg[base0 + 512 + c1]);
            float xr10 = __ldg(&g.xg[base1 + c0]);
            float xz10 = __ldg(&g.xg[base1 + 256 + c0]);
            float xn10 = __ldg(&g.xg[base1 + 512 + c0]);
            float xr11 = __ldg(&g.xg[base1 + c1]);
            float xz11 = __ldg(&g.xg[base1 + 256 + c1]);
            float xn11 = __ldg(&g.xg[base1 + 512 + c1]);
            __syncthreads();

            float aR00 = 0.f, aR01 = 0.f, aR10 = 0.f, aR11 = 0.f;
            float aZ00 = 0.f, aZ01 = 0.f, aZ10 = 0.f, aZ11 = 0.f;
            float aN00 = 0.f, aN01 = 0.f, aN10 = 0.f, aN11 = 0.f;
#pragma unroll 4
            for (int q = 0; q < 64; q++) {
                float4 h0 = h0p[q];
                float4 h1 = h1p[q];
                float4 w;
                w = pr0[q]; aR00 += DOT4(w, h0); aR10 += DOT4(w, h1);
                w = pr1[q]; aR01 += DOT4(w, h0); aR11 += DOT4(w, h1);
                w = pz0[q]; aZ00 += DOT4(w, h0); aZ10 += DOT4(w, h1);
                w = pz1[q]; aZ01 += DOT4(w, h0); aZ11 += DOT4(w, h1);
                w = pn0[q]; aN00 += DOT4(w, h0); aN10 += DOT4(w, h1);
                w = pn1[q]; aN01 += DOT4(w, h0); aN11 += DOT4(w, h1);
            }
            // gate math + stores (cells: [seq-half s][col-half c])
#pragma unroll
            for (int s = 0; s < 2; s++) {
                int sl = sj + 8 * s;
                long long seq = sgrp * 16 + sl;
#pragma unroll
                for (int c = 0; c < 2; c++) {
                    int col = colbase + ci + 16 * c;
                    float aR = s ? (c ? aR11 : aR10) : (c ? aR01 : aR00);
                    float aZ = s ? (c ? aZ11 : aZ10) : (c ? aZ01 : aZ00);
                    float aN = s ? (c ? aN11 : aN10) : (c ? aN01 : aN00);
                    float xr = s ? (c ? xr11 : xr10) : (c ? xr01 : xr00);
                    float xz = s ? (c ? xz11 : xz10) : (c ? xz01 : xz00);
                    float xn = s ? (c ? xn11 : xn10) : (c ? xn01 : xn00);
                    float hr = aR + (c ? br1 : br0);
                    float hz = aZ + (c ? bz1 : bz0);
                    float hn = aN + (c ? bn1 : bn0);
                    float r = 1.f / (1.f + expf(-(xr + hr)));
                    float z = 1.f / (1.f + expf(-(xz + hz)));
                    float n = tanhf(xn + r * hn);
                    float hold = hs[sl * 256 + col];
                    float h = (1.f - z) * n + z * hold;
                    hout[seq * 256 + col] = h;
                    if (g.ys) g.ys[(seq * g.T + t) * 256 + col] = h;
                    if (s) { if (c) mx11 = fmaxf(mx11, h); else mx10 = fmaxf(mx10, h); }
                    else   { if (c) mx01 = fmaxf(mx01, h); else mx00 = fmaxf(mx00, h); }
                }
            }
        }
        grid_barrier(nblocks);
    }
    if (g.hmax) {
        long long s0 = sgrp * 16 + sj, s1 = s0 + 8;
        g.hmax[s0 * 256 + c0] = mx00;
        g.hmax[s0 * 256 + c1] = mx01;
        g.hmax[s1 * 256 + c0] = mx10;
        g.hmax[s1 * 256 + c1] = mx11;
    }
}

// ---------------- final: coef gate, feat, output head, softmax over options ----------------
__global__ void __launch_bounds__(512) final_kernel(
    const float* __restrict__ gate_w, const float* __restrict__ gate_b,
    const float* __restrict__ out_w, const float* __restrict__ out_b,
    float* __restrict__ out) {
    __shared__ float coef[128];
    __shared__ float logits[16];
    int tid = threadIdx.x, w = tid >> 5, lane = tid & 31;
    for (int bon = w; bon < 128; bon += 16) {
        float s = 0.f;
        for (int d = lane; d < 512; d += 32) {
            float rv = (d < 256) ? g_srmax[bon * 256 + d] : g_drmax[bon * 256 + d - 256];
            s += rv * gate_w[d];
        }
#pragma unroll
        for (int off = 16; off; off >>= 1) s += __shfl_xor_sync(0xffffffffu, s, off);
        if (lane == 0) coef[bon] = s + gate_b[0];
    }
    __syncthreads();
    {
        int bo = w;
        float acc = 0.f;
        for (int d = lane; d < 1024; d += 32) {
            float v;
            if (d < 512) {
                float mxv = -1e30f;
#pragma unroll
                for (int n = 0; n < 8; n++) {
                    int bon = bo * 8 + n;
                    float rv = (d < 256) ? g_srmax[bon * 256 + d] : g_drmax[bon * 256 + d - 256];
                    mxv = fmaxf(mxv, coef[bon] * rv);
                }
                v = mxv;
            } else {
                int dd = d - 512;
                float smv = 0.f;
#pragma unroll
                for (int n = 0; n < 8; n++) {
                    int bon = bo * 8 + n;
                    float rv = (dd < 256) ? g_srmax[bon * 256 + dd] : g_drmax[bon * 256 + dd - 256];
                    smv += coef[bon] * rv;
                }
                v = smv * 0.125f;
            }
            acc += v * out_w[d];
        }
#pragma unroll
        for (int off = 16; off; off >>= 1) acc += __shfl_xor_sync(0xffffffffu, acc, off);
        if (lane == 0) logits[bo] = acc + out_b[0];
    }
    __syncthreads();
    if (tid < 4) {
        int b = tid;
        float m = -1e30f;
        for (int o = 0; o < 4; o++) m = fmaxf(m, logits[b * 4 + o]);
        float e[4], s = 0.f;
        for (int o = 0; o < 4; o++) { e[o] = expf(logits[b * 4 + o] - m); s += e[o]; }
        for (int o = 0; o < 4; o++) out[b * 4 + o] = e[o] / s;
    }
}

// ---------------- host orchestration ----------------
#define SYM(p, s) do { void* _t = nullptr; cudaGetSymbolAddress(&_t, s); p = (float*)_t; } while (0)

static const int GRU_SMEM = (96 * WP + 16 * 256) * 4;  // 116,224 B

extern "C" void kernel_launch(void* const* d_in, const int* in_sizes, int n_in,
                              void* d_out, int out_size) {
    const float* statement = (const float*)d_in[0];
    const float* answer    = (const float*)d_in[1];
    const float* refs      = (const float*)d_in[2];
    const float* ctx_wih   = (const float*)d_in[3];
    const float* ctx_whh   = (const float*)d_in[4];
    const float* ctx_bih   = (const float*)d_in[5];
    const float* ctx_bhh   = (const float*)d_in[6];
    const float* sr_wih    = (const float*)d_in[7];
    const float* sr_whh    = (const float*)d_in[8];
    const float* sr_bih    = (const float*)d_in[9];
    const float* sr_bhh    = (const float*)d_in[10];
    const float* dr_wih    = (const float*)d_in[11];
    const float* dr_whh    = (const float*)d_in[12];
    const float* dr_bih    = (const float*)d_in[13];
    const float* dr_bhh    = (const float*)d_in[14];
    const float* gate_w    = (const float*)d_in[15];
    const float* gate_b    = (const float*)d_in[16];
    const float* out_w     = (const float*)d_in[17];
    const float* out_b     = (const float*)d_in[18];
    float* out = (float*)d_out;

    float *stmt_in, *xg_stmt, *stmt_h, *xg_docs, *docs_h;
    float *hs0, *hs1, *hd0, *hd1;
    float *matchb, *p1, *p2t, *read_sum, *doc_read, *dri, *mmb, *att;
    float *xg_sr, *xg_dr, *hsr0, *hsr1, *hdr0, *hdr1, *srmax, *drmax;
    SYM(stmt_in, g_stmt_in); SYM(xg_stmt, g_xg_stmt); SYM(stmt_h, g_stmt_h);
    SYM(xg_docs, g_xg_docs); SYM(docs_h, g_docs_h);
    SYM(hs0, g_hs0); SYM(hs1, g_hs1); SYM(hd0, g_hd0); SYM(hd1, g_hd1);
    SYM(matchb, g_match); SYM(p1, g_p1); SYM(p2t, g_p2t);
    SYM(read_sum, g_read_sum); SYM(doc_read, g_doc_read); SYM(dri, g_dri);
    SYM(mmb, g_mm); SYM(att, g_att);
    SYM(xg_sr, g_xg_sr); SYM(xg_dr, g_xg_dr);
    SYM(hsr0, g_hsr0); SYM(hsr1, g_hsr1); SYM(hdr0, g_hdr0); SYM(hdr1, g_hdr1);
    SYM(srmax, g_srmax); SYM(drmax, g_drmax);

    cudaFuncSetAttribute(gru_phase, cudaFuncAttributeMaxDynamicSharedMemorySize, GRU_SMEM);

    init_state<<<128, 256>>>();
    concat_stmt<<<4096, 256>>>(statement, answer);

    // input projections for ctx GRU
    gemm128<1><<<dim3(6, 32, 1), 256>>>(stmt_in, ctx_wih, ctx_bih, xg_stmt,
                                        4096, 768, 256, 0, 0, 0, 1, 1);
    gemm128<1><<<dim3(6, 128, 1), 256>>>(refs, ctx_wih, ctx_bih, xg_docs,
                                         16384, 768, 256, 0, 0, 0, 1, 1);

    // phase A: persistent ctx GRU — stmt (16 seqs, T=256) || docs (128 seqs, T=128)
    {
        GG gs; gs.xg = xg_stmt; gs.whh = ctx_whh; gs.bhh = ctx_bhh;
        gs.h0 = hs0; gs.h1 = hs1; gs.ys = stmt_h; gs.hmax = nullptr;
        gs.T = 256; gs.nsg = 1;
        GG gd; gd.xg = xg_docs; gd.whh = ctx_whh; gd.bhh = ctx_bhh;
        gd.h0 = hd0; gd.h1 = hd1; gd.ys = docs_h; gd.hmax = nullptr;
        gd.T = 128; gd.nsg = 8;
        gru_phase<<<72, 128, GRU_SMEM>>>(gs, gd);  // 72 blocks <= 148 SMs, 1/SM
    }

    // match[bon][s][l] = stmt[bo,s,:] . docs[bon,l,:]
    gemm128<1><<<dim3(1, 2, 128), 256>>>(stmt_h, docs_h, nullptr, matchb,
                                         256, 128, 256, 65536, 32768, 32768, 8, 1);
    softmax_rows<<<32768, 256>>>(matchb, p1, 128);
    softmax_cols_t<<<dim3(32, 128), 128>>>();
    // read_sum = p1 @ docs ; doc_read = p2t @ stmt
    gemm128<0><<<dim3(2, 2, 128), 256>>>(p1, docs_h, nullptr, read_sum,
                                         256, 256, 128, 32768, 32768, 65536, 1, 1);
    gemm128<0><<<dim3(2, 1, 128), 256>>>(p2t, stmt_h, nullptr, doc_read,
                                         128, 256, 256, 32768, 65536, 32768, 1, 8);
    concat_dri<<<4096, 256>>>();

    // doc-doc cross attention per bo: mm = dri @ dri^T ; softmax ; att = p3 @ dri
    gemm128<1><<<dim3(8, 8, 16), 256>>>(dri, dri, nullptr, mmb,
                                        1024, 1024, 512, 524288, 524288, 1048576, 1, 1);
    softmax_rows<<<16384, 256>>>(mmb, mmb, 1024);
    gemm128<0><<<dim3(4, 8, 16), 256>>>(mmb, dri, nullptr, att,
                                        1024, 512, 1024, 1048576, 524288, 524288, 1, 1);

    // input projections for reasoning GRUs
    gemm128<1><<<dim3(6, 256, 1), 256>>>(read_sum, sr_wih, sr_bih, xg_sr,
                                         32768, 768, 256, 0, 0, 0, 1, 1);
    gemm128<1><<<dim3(6, 128, 1), 256>>>(att, dr_wih, dr_bih, xg_dr,
                                         16384, 768, 512, 0, 0, 0, 1, 1);

    // phase C: persistent reasoning GRUs — sr (128 seqs, T=256) || dr (128 seqs, T=128)
    {
        GG ga; ga.xg = xg_sr; ga.whh = sr_whh; ga.bhh = sr_bhh;
        ga.h0 = hsr0; ga.h1 = hsr1; ga.ys = nullptr; ga.hmax = srmax;
        ga.T = 256; ga.nsg = 8;
        GG gb; gb.xg = xg_dr; gb.whh = dr_whh; gb.bhh = dr_bhh;
        gb.h0 = hdr0; gb.h1 = hdr1; gb.ys = nullptr; gb.hmax = drmax;
        gb.T = 128; gb.nsg = 8;
        gru_phase<<<128, 128, GRU_SMEM>>>(ga, gb);  // 128 blocks <= 148 SMs, 1/SM
    }

    final_kernel<<<1, 512>>>(gate_w, gate_b, out_w, out_b, out);
}

// round 6
// speedup vs baseline: 1.5375x; 1.1646x over previous
#include <cuda_runtime.h>
#include <math.h>

// Problem dims: B=4 O=4 L=128 N=8 V=256 H=256, Ls=2L=256, BO=16, BON=128, NL=1024

// ---------------- scratch (device globals; no allocation allowed) ----------------
__device__ float g_stmt_in[16 * 256 * 256];
__device__ float g_xg_stmt[16 * 256 * 768];
__device__ float g_stmt_h[16 * 256 * 256];
__device__ float g_xg_docs[128 * 128 * 768];
__device__ float g_docs_h[128 * 128 * 256];
__device__ float g_hs0[16 * 256], g_hs1[16 * 256];
__device__ float g_hd0[128 * 256], g_hd1[128 * 256];
__device__ float g_match[128 * 256 * 128];
__device__ float g_p1[128 * 256 * 128];
__device__ float g_p2t[128 * 128 * 256];
__device__ float g_read_sum[128 * 256 * 256];
__device__ float g_doc_read[128 * 128 * 256];
__device__ float g_dri[128 * 128 * 512];
__device__ float g_mm[16 * 1024 * 1024];
__device__ float g_att[128 * 128 * 512];
__device__ float g_xg_sr[128 * 256 * 768];
__device__ float g_xg_dr[128 * 128 * 768];
__device__ float g_hsr0[128 * 256], g_hsr1[128 * 256];
__device__ float g_hdr0[128 * 256], g_hdr1[128 * 256];
__device__ float g_srmax[128 * 256], g_drmax[128 * 256];

__device__ unsigned int g_bar_count;
__device__ unsigned int g_bar_gen;

// ---------------- init ----------------
__global__ void init_state() {
    int i = blockIdx.x * 256 + threadIdx.x;  // 32768 threads
    if (i == 0) { g_bar_count = 0; g_bar_gen = 0; }
    if (i < 16 * 256) { g_hs0[i] = 0.f; g_hs1[i] = 0.f; }
    if (i < 128 * 256) {
        g_hd0[i] = 0.f;  g_hd1[i] = 0.f;
        g_hsr0[i] = 0.f; g_hsr1[i] = 0.f;
        g_hdr0[i] = 0.f; g_hdr1[i] = 0.f;
    }
}

// ---------------- build stmt = cat(question, answer) ----------------
__global__ void concat_stmt(const float* __restrict__ statement,
                            const float* __restrict__ answer) {
    int idx = blockIdx.x * 256 + threadIdx.x;  // 1048576
    int v = idx & 255;
    int s = (idx >> 8) & 255;
    int bo = idx >> 16;
    int b = bo >> 2;
    float val;
    if (s < 128) val = statement[(b * 128 + s) * 256 + v];
    else         val = answer[(bo * 128 + (s - 128)) * 256 + v];
    g_stmt_in[idx] = val;
}

// ---------------- dri = cat(docs, doc_read) ----------------
__global__ void concat_dri() {
    for (int idx = blockIdx.x * blockDim.x + threadIdx.x; idx < 128 * 128 * 512;
         idx += gridDim.x * blockDim.x) {
        int h = idx & 511;
        int rest = idx >> 9;
        g_dri[idx] = (h < 256) ? g_docs_h[rest * 256 + h]
                               : g_doc_read[rest * 256 + (h - 256)];
    }
}

// ---------------- tf32 tensor-core GEMM ----------------
__device__ __forceinline__ unsigned f2tf(float x) {
    unsigned r;
    asm("cvt.rna.tf32.f32 %0, %1;" : "=r"(r) : "f"(x));
    return r;
}

__device__ __forceinline__ void mma_tf32(float4& d, const unsigned* a, const unsigned* b) {
    asm volatile(
        "mma.sync.aligned.m16n8k8.row.col.f32.tf32.tf32.f32 "
        "{%0,%1,%2,%3}, {%4,%5,%6,%7}, {%8,%9}, {%0,%1,%2,%3};"
        : "+f"(d.x), "+f"(d.y), "+f"(d.z), "+f"(d.w)
        : "r"(a[0]), "r"(a[1]), "r"(a[2]), "r"(a[3]), "r"(b[0]), "r"(b[1]));
}

// Tile 128x128, K-tile 32, 256 threads (8 warps, each 64x32).
// TB=1: C = A[M,K] * B[N,K]^T (+bias);  TB=0: C = A[M,K] * B[K,N] (+bias)
// Requires M,N multiples of 128 and K multiple of 32.
template <int TB>
__global__ void __launch_bounds__(256) gemm_tf32(
    const float* __restrict__ A, const float* __restrict__ B,
    const float* __restrict__ bias, float* __restrict__ C,
    int N, int K, long long sA, long long sB, long long sC,
    int divA, int divB) {
    const int tid = threadIdx.x;
    int z = blockIdx.z;
    A += (long long)(z / divA) * sA + (long long)(blockIdx.y * 128) * K;
    if (TB) B += (long long)(z / divB) * sB + (long long)(blockIdx.x * 128) * K;
    else    B += (long long)(z / divB) * sB + blockIdx.x * 128;
    C += (long long)z * sC + (long long)(blockIdx.y * 128) * N + blockIdx.x * 128;

    __shared__ unsigned As[128 * 36];   // [m][k], pitch 36 -> conflict-free frags
    __shared__ unsigned Bs[128 * 36];   // TN: [n][k] pitch 36; NN: [k][n] pitch 132

    const int warp = tid >> 5, lane = tid & 31;
    const int wm = (warp & 1) * 64, wn = (warp >> 1) * 32;
    const int lq = lane >> 2, lr = lane & 3;

    // staging indices
    const int sm = tid >> 3;         // 0..31 (row group, +32*i)
    const int sk = (tid & 7) * 4;    // 0..28
    const int bk = tid >> 5;         // 0..7 (NN k row, +8*i)
    const int bn = (tid & 31) * 4;   // 0..124

    float4 acc[4][4];
#pragma unroll
    for (int i = 0; i < 4; i++)
#pragma unroll
        for (int j = 0; j < 4; j++) acc[i][j] = make_float4(0.f, 0.f, 0.f, 0.f);

    float4 pa[4], pb[4];
    // load first tile
#pragma unroll
    for (int i = 0; i < 4; i++)
        pa[i] = *reinterpret_cast<const float4*>(&A[(long long)(sm + 32 * i) * K + sk]);
    if (TB) {
#pragma unroll
        for (int i = 0; i < 4; i++)
            pb[i] = *reinterpret_cast<const float4*>(&B[(long long)(sm + 32 * i) * K + sk]);
    } else {
#pragma unroll
        for (int i = 0; i < 4; i++)
            pb[i] = *reinterpret_cast<const float4*>(&B[(long long)(bk + 8 * i) * N + bn]);
    }

    int k0 = 0;
    for (;;) {
        // store staged tile to smem (convert to tf32)
#pragma unroll
        for (int i = 0; i < 4; i++) {
            uint4 u;
            u.x = f2tf(pa[i].x); u.y = f2tf(pa[i].y); u.z = f2tf(pa[i].z); u.w = f2tf(pa[i].w);
            *reinterpret_cast<uint4*>(&As[(sm + 32 * i) * 36 + sk]) = u;
        }
#pragma unroll
        for (int i = 0; i < 4; i++) {
            uint4 u;
            u.x = f2tf(pb[i].x); u.y = f2tf(pb[i].y); u.z = f2tf(pb[i].z); u.w = f2tf(pb[i].w);
            if (TB) *reinterpret_cast<uint4*>(&Bs[(sm + 32 * i) * 36 + sk]) = u;
            else    *reinterpret_cast<uint4*>(&Bs[(bk + 8 * i) * 132 + bn]) = u;
        }
        __syncthreads();

        int k1 = k0 + 32;
        if (k1 < K) {  // prefetch next tile into regs
#pragma unroll
            for (int i = 0; i < 4; i++)
                pa[i] = *reinterpret_cast<const float4*>(&A[(long long)(sm + 32 * i) * K + k1 + sk]);
            if (TB) {
#pragma unroll
                for (int i = 0; i < 4; i++)
                    pb[i] = *reinterpret_cast<const float4*>(&B[(long long)(sm + 32 * i) * K + k1 + sk]);
            } else {
#pragma unroll
                for (int i = 0; i < 4; i++)
                    pb[i] = *reinterpret_cast<const float4*>(&B[(long long)(k1 + bk + 8 * i) * N + bn]);
            }
        }

        // compute on current smem tile
#pragma unroll
        for (int kk = 0; kk < 32; kk += 8) {
            unsigned a[4][4];
#pragma unroll
            for (int mt = 0; mt < 4; mt++) {
                int r = (wm + mt * 16 + lq) * 36 + kk + lr;
                a[mt][0] = As[r];
                a[mt][1] = As[r + 8 * 36];
                a[mt][2] = As[r + 4];
                a[mt][3] = As[r + 8 * 36 + 4];
            }
            unsigned b[4][2];
#pragma unroll
            for (int nt = 0; nt < 4; nt++) {
                if (TB) {
                    int r = (wn + nt * 8 + lq) * 36 + kk + lr;
                    b[nt][0] = Bs[r];
                    b[nt][1] = Bs[r + 4];
                } else {
                    int r = (kk + lr) * 132 + wn + nt * 8 + lq;
                    b[nt][0] = Bs[r];
                    b[nt][1] = Bs[r + 4 * 132];
                }
            }
#pragma unroll
            for (int mt = 0; mt < 4; mt++)
#pragma unroll
                for (int nt = 0; nt < 4; nt++) mma_tf32(acc[mt][nt], a[mt], b[nt]);
        }
        if (k1 >= K) break;
        __syncthreads();
        k0 = k1;
    }

    // epilogue
#pragma unroll
    for (int nt = 0; nt < 4; nt++) {
        int col = wn + nt * 8 + 2 * lr;
        float bx = 0.f, by = 0.f;
        if (bias) {
            int cg = blockIdx.x * 128 + col;
            bx = bias[cg]; by = bias[cg + 1];
        }
#pragma unroll
        for (int mt = 0; mt < 4; mt++) {
            int row = wm + mt * 16 + lq;
            float4 v = acc[mt][nt];
            float2 v0 = make_float2(v.x + bx, v.y + by);
            float2 v1 = make_float2(v.z + bx, v.w + by);
            *reinterpret_cast<float2*>(&C[(long long)row * N + col]) = v0;
            *reinterpret_cast<float2*>(&C[(long long)(row + 8) * N + col]) = v1;
        }
    }
}

// ---------------- softmax: 1024 cols, block per row, regs-resident ----------------
__global__ void __launch_bounds__(256) softmax_block1024(const float* __restrict__ in,
                                                         float* __restrict__ out) {
    long long row = blockIdx.x;
    const float4* x = reinterpret_cast<const float4*>(in + row * 1024);
    float4* y = reinterpret_cast<float4*>(out + row * 1024);
    int tid = threadIdx.x, warp = tid >> 5, lane = tid & 31;
    __shared__ float redm[8], reds[8];
    float4 v = x[tid];
    float m = fmaxf(fmaxf(v.x, v.y), fmaxf(v.z, v.w));
#pragma unroll
    for (int off = 16; off; off >>= 1) m = fmaxf(m, __shfl_xor_sync(0xffffffffu, m, off));
    if (lane == 0) redm[warp] = m;
    __syncthreads();
    m = redm[0];
#pragma unroll
    for (int i = 1; i < 8; i++) m = fmaxf(m, redm[i]);
    v.x = expf(v.x - m); v.y = expf(v.y - m); v.z = expf(v.z - m); v.w = expf(v.w - m);
    float s = v.x + v.y + v.z + v.w;
#pragma unroll
    for (int off = 16; off; off >>= 1) s += __shfl_xor_sync(0xffffffffu, s, off);
    if (lane == 0) reds[warp] = s;
    __syncthreads();
    s = reds[0];
#pragma unroll
    for (int i = 1; i < 8; i++) s += reds[i];
    float inv = 1.f / s;
    v.x *= inv; v.y *= inv; v.z *= inv; v.w *= inv;
    y[tid] = v;
}

// ---------------- softmax: 128 cols, warp per row (8 rows per block) ----------------
__global__ void __launch_bounds__(256) softmax_warp128(const float* __restrict__ in,
                                                       float* __restrict__ out) {
    int warp = threadIdx.x >> 5, lane = threadIdx.x & 31;
    long long row = (long long)blockIdx.x * 8 + warp;
    const float4* x = reinterpret_cast<const float4*>(in + row * 128);
    float4* y = reinterpret_cast<float4*>(out + row * 128);
    float4 v = x[lane];
    float m = fmaxf(fmaxf(v.x, v.y), fmaxf(v.z, v.w));
#pragma unroll
    for (int off = 16; off; off >>= 1) m = fmaxf(m, __shfl_xor_sync(0xffffffffu, m, off));
    v.x = expf(v.x - m); v.y = expf(v.y - m); v.z = expf(v.z - m); v.w = expf(v.w - m);
    float s = v.x + v.y + v.z + v.w;
#pragma unroll
    for (int off = 16; off; off >>= 1) s += __shfl_xor_sync(0xffffffffu, s, off);
    float inv = 1.f / s;
    v.x *= inv; v.y *= inv; v.z *= inv; v.w *= inv;
    y[lane] = v;
}

// ---------------- column softmax of match over s, output transposed [bon][l][s] ----------------
__global__ void __launch_bounds__(128) softmax_cols_t() {
    int bon = blockIdx.y;
    int l = blockIdx.x * 4 + (threadIdx.x >> 5);
    int lane = threadIdx.x & 31;
    const float* base = g_match + (long long)bon * 256 * 128 + l;
    float v[8];
    float m = -1e30f;
#pragma unroll
    for (int i = 0; i < 8; i++) {
        v[i] = base[(lane + 32 * i) * 128];
        m = fmaxf(m, v[i]);
    }
#pragma unroll
    for (int off = 16; off; off >>= 1) m = fmaxf(m, __shfl_xor_sync(0xffffffffu, m, off));
    float sum = 0.f;
#pragma unroll
    for (int i = 0; i < 8; i++) { v[i] = expf(v[i] - m); sum += v[i]; }
#pragma unroll
    for (int off = 16; off; off >>= 1) sum += __shfl_xor_sync(0xffffffffu, sum, off);
    float inv = 1.f / sum;
    float* o = g_p2t + ((long long)bon * 128 + l) * 256;
#pragma unroll
    for (int i = 0; i < 8; i++) o[lane + 32 * i] = v[i] * inv;
}

// ---------------- grid barrier (all blocks resident by construction) ----------------
__device__ __forceinline__ void grid_barrier(unsigned nblocks) {
    __syncthreads();
    if (threadIdx.x == 0) {
        volatile unsigned* genp = &g_bar_gen;
        unsigned gen = *genp;
        __threadfence();
        unsigned old = atomicAdd(&g_bar_count, 1u);
        if (old == nblocks - 1) {
            *((volatile unsigned*)&g_bar_count) = 0;
            __threadfence();
            *genp = gen + 1;
        } else {
            while (*genp == gen) {}
        }
        __threadfence();
    }
    __syncthreads();
}

// ---------------- persistent fused GRU phase ----------------
struct GG {
    const float* xg;    // [nseq][T][768]
    const float* whh;   // [768][256]
    const float* bhh;   // [768]
    float* h0;          // [nseq][256] (t even input)
    float* h1;
    float* ys;          // optional [nseq][T][256]
    float* hmax;        // optional [nseq][256]
    int T;
    int nsg;            // seq groups of 16
};

#define WP 260  // padded weight row pitch (floats)
#define DOT4(w, h) ((w).x * (h).x + (w).y * (h).y + (w).z * (h).z + (w).w * (h).w)

// block = 128 threads, tile = 16 seqs x 32 cols. grid = (ga.nsg + gb.nsg) * 8 blocks.
__global__ void __launch_bounds__(128) gru_phase(GG ga, GG gb) {
    extern __shared__ float sm[];
    float* ws = sm;               // 96 x WP
    float* hs = sm + 96 * WP;     // 16 x 256

    GG g;
    int sgrp, colbase;
    {
        int b = blockIdx.x;
        int blocks0 = ga.nsg * 8;
        if (b < blocks0) { g = ga; sgrp = b >> 3; colbase = (b & 7) * 32; }
        else { g = gb; int bb = b - blocks0; sgrp = bb >> 3; colbase = (bb & 7) * 32; }
    }
    const int tid = threadIdx.x;
    const int ci = tid & 15;
    const int sj = tid >> 4;  // 0..7
    const unsigned nblocks = gridDim.x;

    // load weight slice: rows {gate*256 + colbase + j}, j in [0,32), all 256 k
    for (int i = tid; i < 96 * 64; i += 128) {
        int r = i >> 6, q = i & 63;
        float4 v = __ldg(reinterpret_cast<const float4*>(
            &g.whh[(long long)((r >> 5) * 256 + colbase + (r & 31)) * 256 + q * 4]));
        *reinterpret_cast<float4*>(&ws[r * WP + q * 4]) = v;
    }
    const int c0 = colbase + ci, c1 = c0 + 16;
    const float br0 = g.bhh[c0], bz0 = g.bhh[256 + c0], bn0 = g.bhh[512 + c0];
    const float br1 = g.bhh[c1], bz1 = g.bhh[256 + c1], bn1 = g.bhh[512 + c1];
    float mx00 = -1e30f, mx01 = -1e30f, mx10 = -1e30f, mx11 = -1e30f;

    const float4* pr0 = reinterpret_cast<const float4*>(&ws[(0 * 32 + ci) * WP]);
    const float4* pr1 = reinterpret_cast<const float4*>(&ws[(0 * 32 + ci + 16) * WP]);
    const float4* pz0 = reinterpret_cast<const float4*>(&ws[(1 * 32 + ci) * WP]);
    const float4* pz1 = reinterpret_cast<const float4*>(&ws[(1 * 32 + ci + 16) * WP]);
    const float4* pn0 = reinterpret_cast<const float4*>(&ws[(2 * 32 + ci) * WP]);
    const float4* pn1 = reinterpret_cast<const float4*>(&ws[(2 * 32 + ci + 16) * WP]);
    const float4* h0p = reinterpret_cast<const float4*>(&hs[sj * 256]);
    const float4* h1p = reinterpret_cast<const float4*>(&hs[(sj + 8) * 256]);

    for (int t = 0; t < 256; t++) {
        if (t < g.T) {
            const float* hin = (t & 1) ? g.h1 : g.h0;
            float* hout = (t & 1) ? g.h0 : g.h1;
            const float* tilebase = hin + (long long)sgrp * 16 * 256;
            // stage h tile [16][256] (L2-only loads: written by other SMs last step)
#pragma unroll
            for (int i = 0; i < 8; i++) {
                int idx = tid + i * 128;  // 0..1023 float4
                float4 v = __ldcg(reinterpret_cast<const float4*>(tilebase) + idx);
                *reinterpret_cast<float4*>(&hs[idx * 4]) = v;
            }
            // prefetch xg for this thread's 4 cells (overlaps with compute)
            const long long base0 = ((long long)(sgrp * 16 + sj) * g.T + t) * 768;
            const long long base1 = ((long long)(sgrp * 16 + sj + 8) * g.T + t) * 768;
            float xr00 = __ldg(&g.xg[base0 + c0]);
            float xz00 = __ldg(&g.xg[base0 + 256 + c0]);
            float xn00 = __ldg(&g.xg[base0 + 512 + c0]);
            float xr01 = __ldg(&g.xg[base0 + c1]);
            float xz01 = __ldg(&g.xg[base0 + 256 + c1]);
            float xn01 = __ldg(&g.xg[base0 + 512 + c1]);
            float xr10 = __ldg(&g.xg[base1 + c0]);
            float xz10 = __ldg(&g.xg[base1 + 256 + c0]);
            float xn10 = __ldg(&g.xg[base1 + 512 + c0]);
            float xr11 = __ldg(&g.xg[base1 + c1]);
            float xz11 = __ldg(&g.xg[base1 + 256 + c1]);
            float xn11 = __ldg(&g.xg[base1 + 512 + c1]);
            __syncthreads();

            float aR00 = 0.f, aR01 = 0.f, aR10 = 0.f, aR11 = 0.f;
            float aZ00 = 0.f, aZ01 = 0.f, aZ10 = 0.f, aZ11 = 0.f;
            float aN00 = 0.f, aN01 = 0.f, aN10 = 0.f, aN11 = 0.f;
#pragma unroll 4
            for (int q = 0; q < 64; q++) {
                float4 h0 = h0p[q];
                float4 h1 = h1p[q];
                float4 w;
                w = pr0[q]; aR00 += DOT4(w, h0); aR10 += DOT4(w, h1);
                w = pr1[q]; aR01 += DOT4(w, h0); aR11 += DOT4(w, h1);
                w = pz0[q]; aZ00 += DOT4(w, h0); aZ10 += DOT4(w, h1);
                w = pz1[q]; aZ01 += DOT4(w, h0); aZ11 += DOT4(w, h1);
                w = pn0[q]; aN00 += DOT4(w, h0); aN10 += DOT4(w, h1);
                w = pn1[q]; aN01 += DOT4(w, h0); aN11 += DOT4(w, h1);
            }
            // gate math + stores (cells: [seq-half s][col-half c])
#pragma unroll
            for (int s = 0; s < 2; s++) {
                int sl = sj + 8 * s;
                long long seq = sgrp * 16 + sl;
#pragma unroll
                for (int c = 0; c < 2; c++) {
                    int col = colbase + ci + 16 * c;
                    float aR = s ? (c ? aR11 : aR10) : (c ? aR01 : aR00);
                    float aZ = s ? (c ? aZ11 : aZ10) : (c ? aZ01 : aZ00);
                    float aN = s ? (c ? aN11 : aN10) : (c ? aN01 : aN00);
                    float xr = s ? (c ? xr11 : xr10) : (c ? xr01 : xr00);
                    float xz = s ? (c ? xz11 : xz10) : (c ? xz01 : xz00);
                    float xn = s ? (c ? xn11 : xn10) : (c ? xn01 : xn00);
                    float hr = aR + (c ? br1 : br0);
                    float hz = aZ + (c ? bz1 : bz0);
                    float hn = aN + (c ? bn1 : bn0);
                    float r = 1.f / (1.f + expf(-(xr + hr)));
                    float z = 1.f / (1.f + expf(-(xz + hz)));
                    float n = tanhf(xn + r * hn);
                    float hold = hs[sl * 256 + col];
                    float h = (1.f - z) * n + z * hold;
                    hout[seq * 256 + col] = h;
                    if (g.ys) g.ys[(seq * g.T + t) * 256 + col] = h;
                    if (s) { if (c) mx11 = fmaxf(mx11, h); else mx10 = fmaxf(mx10, h); }
                    else   { if (c) mx01 = fmaxf(mx01, h); else mx00 = fmaxf(mx00, h); }
                }
            }
        }
        grid_barrier(nblocks);
    }
    if (g.hmax) {
        long long s0 = sgrp * 16 + sj, s1 = s0 + 8;
        g.hmax[s0 * 256 + c0] = mx00;
        g.hmax[s0 * 256 + c1] = mx01;
        g.hmax[s1 * 256 + c0] = mx10;
        g.hmax[s1 * 256 + c1] = mx11;
    }
}

// ---------------- final: coef gate, feat, output head, softmax over options ----------------
__global__ void __launch_bounds__(512) final_kernel(
    const float* __restrict__ gate_w, const float* __restrict__ gate_b,
    const float* __restrict__ out_w, const float* __restrict__ out_b,
    float* __restrict__ out) {
    __shared__ float coef[128];
    __shared__ float logits[16];
    int tid = threadIdx.x, w = tid >> 5, lane = tid & 31;
    for (int bon = w; bon < 128; bon += 16) {
        float s = 0.f;
        for (int d = lane; d < 512; d += 32) {
            float rv = (d < 256) ? g_srmax[bon * 256 + d] : g_drmax[bon * 256 + d - 256];
            s += rv * gate_w[d];
        }
#pragma unroll
        for (int off = 16; off; off >>= 1) s += __shfl_xor_sync(0xffffffffu, s, off);
        if (lane == 0) coef[bon] = s + gate_b[0];
    }
    __syncthreads();
    {
        int bo = w;
        float acc = 0.f;
        for (int d = lane; d < 1024; d += 32) {
            float v;
            if (d < 512) {
                float mxv = -1e30f;
#pragma unroll
                for (int n = 0; n < 8; n++) {
                    int bon = bo * 8 + n;
                    float rv = (d < 256) ? g_srmax[bon * 256 + d] : g_drmax[bon * 256 + d - 256];
                    mxv = fmaxf(mxv, coef[bon] * rv);
                }
                v = mxv;
            } else {
                int dd = d - 512;
                float smv = 0.f;
#pragma unroll
                for (int n = 0; n < 8; n++) {
                    int bon = bo * 8 + n;
                    float rv = (dd < 256) ? g_srmax[bon * 256 + dd] : g_drmax[bon * 256 + dd - 256];
                    smv += coef[bon] * rv;
                }
                v = smv * 0.125f;
            }
            acc += v * out_w[d];
        }
#pragma unroll
        for (int off = 16; off; off >>= 1) acc += __shfl_xor_sync(0xffffffffu, acc, off);
        if (lane == 0) logits[bo] = acc + out_b[0];
    }
    __syncthreads();
    if (tid < 4) {
        int b = tid;
        float m = -1e30f;
        for (int o = 0; o < 4; o++) m = fmaxf(m, logits[b * 4 + o]);
        float e[4], s = 0.f;
        for (int o = 0; o < 4; o++) { e[o] = expf(logits[b * 4 + o] - m); s += e[o]; }
        for (int o = 0; o < 4; o++) out[b * 4 + o] = e[o] / s;
    }
}

// ---------------- host orchestration ----------------
#define SYM(p, s) do { void* _t = nullptr; cudaGetSymbolAddress(&_t, s); p = (float*)_t; } while (0)

static const int GRU_SMEM = (96 * WP + 16 * 256) * 4;  // 116,224 B

extern "C" void kernel_launch(void* const* d_in, const int* in_sizes, int n_in,
                              void* d_out, int out_size) {
    const float* statement = (const float*)d_in[0];
    const float* answer    = (const float*)d_in[1];
    const float* refs      = (const float*)d_in[2];
    const float* ctx_wih   = (const float*)d_in[3];
    const float* ctx_whh   = (const float*)d_in[4];
    const float* ctx_bih   = (const float*)d_in[5];
    const float* ctx_bhh   = (const float*)d_in[6];
    const float* sr_wih    = (const float*)d_in[7];
    const float* sr_whh    = (const float*)d_in[8];
    const float* sr_bih    = (const float*)d_in[9];
    const float* sr_bhh    = (const float*)d_in[10];
    const float* dr_wih    = (const float*)d_in[11];
    const float* dr_whh    = (const float*)d_in[12];
    const float* dr_bih    = (const float*)d_in[13];
    const float* dr_bhh    = (const float*)d_in[14];
    const float* gate_w    = (const float*)d_in[15];
    const float* gate_b    = (const float*)d_in[16];
    const float* out_w     = (const float*)d_in[17];
    const float* out_b     = (const float*)d_in[18];
    float* out = (float*)d_out;

    float *stmt_in, *xg_stmt, *stmt_h, *xg_docs, *docs_h;
    float *hs0, *hs1, *hd0, *hd1;
    float *matchb, *p1, *p2t, *read_sum, *doc_read, *dri, *mmb, *att;
    float *xg_sr, *xg_dr, *hsr0, *hsr1, *hdr0, *hdr1, *srmax, *drmax;
    SYM(stmt_in, g_stmt_in); SYM(xg_stmt, g_xg_stmt); SYM(stmt_h, g_stmt_h);
    SYM(xg_docs, g_xg_docs); SYM(docs_h, g_docs_h);
    SYM(hs0, g_hs0); SYM(hs1, g_hs1); SYM(hd0, g_hd0); SYM(hd1, g_hd1);
    SYM(matchb, g_match); SYM(p1, g_p1); SYM(p2t, g_p2t);
    SYM(read_sum, g_read_sum); SYM(doc_read, g_doc_read); SYM(dri, g_dri);
    SYM(mmb, g_mm); SYM(att, g_att);
    SYM(xg_sr, g_xg_sr); SYM(xg_dr, g_xg_dr);
    SYM(hsr0, g_hsr0); SYM(hsr1, g_hsr1); SYM(hdr0, g_hdr0); SYM(hdr1, g_hdr1);
    SYM(srmax, g_srmax); SYM(drmax, g_drmax);

    cudaFuncSetAttribute(gru_phase, cudaFuncAttributeMaxDynamicSharedMemorySize, GRU_SMEM);

    init_state<<<128, 256>>>();
    concat_stmt<<<4096, 256>>>(statement, answer);

    // input projections for ctx GRU (TN: W is [768, in])
    gemm_tf32<1><<<dim3(6, 32, 1), 256>>>(stmt_in, ctx_wih, ctx_bih, xg_stmt,
                                          768, 256, 0, 0, 0, 1, 1);
    gemm_tf32<1><<<dim3(6, 128, 1), 256>>>(refs, ctx_wih, ctx_bih, xg_docs,
                                           768, 256, 0, 0, 0, 1, 1);

    // phase A: persistent ctx GRU — stmt (16 seqs, T=256) || docs (128 seqs, T=128)
    {
        GG gs; gs.xg = xg_stmt; gs.whh = ctx_whh; gs.bhh = ctx_bhh;
        gs.h0 = hs0; gs.h1 = hs1; gs.ys = stmt_h; gs.hmax = nullptr;
        gs.T = 256; gs.nsg = 1;
        GG gd; gd.xg = xg_docs; gd.whh = ctx_whh; gd.bhh = ctx_bhh;
        gd.h0 = hd0; gd.h1 = hd1; gd.ys = docs_h; gd.hmax = nullptr;
        gd.T = 128; gd.nsg = 8;
        gru_phase<<<72, 128, GRU_SMEM>>>(gs, gd);  // 72 blocks <= 148 SMs, 1/SM
    }

    // match[bon][s][l] = stmt[bo,s,:] . docs[bon,l,:]
    gemm_tf32<1><<<dim3(1, 2, 128), 256>>>(stmt_h, docs_h, nullptr, matchb,
                                           128, 256, 65536, 32768, 32768, 8, 1);
    softmax_warp128<<<4096, 256>>>(matchb, p1);
    softmax_cols_t<<<dim3(32, 128), 128>>>();
    // read_sum = p1 @ docs ; doc_read = p2t @ stmt
    gemm_tf32<0><<<dim3(2, 2, 128), 256>>>(p1, docs_h, nullptr, read_sum,
                                           256, 128, 32768, 32768, 65536, 1, 1);
    gemm_tf32<0><<<dim3(2, 1, 128), 256>>>(p2t, stmt_h, nullptr, doc_read,
                                           256, 256, 32768, 65536, 32768, 1, 8);
    concat_dri<<<4096, 256>>>();

    // doc-doc cross attention per bo: mm = dri @ dri^T ; softmax ; att = p3 @ dri
    gemm_tf32<1><<<dim3(8, 8, 16), 256>>>(dri, dri, nullptr, mmb,
                                          1024, 512, 524288, 524288, 1048576, 1, 1);
    softmax_block1024<<<16384, 256>>>(mmb, mmb);
    gemm_tf32<0><<<dim3(4, 8, 16), 256>>>(mmb, dri, nullptr, att,
                                          512, 1024, 1048576, 524288, 524288, 1, 1);

    // input projections for reasoning GRUs
    gemm_tf32<1><<<dim3(6, 256, 1), 256>>>(read_sum, sr_wih, sr_bih, xg_sr,
                                           768, 256, 0, 0, 0, 1, 1);
    gemm_tf32<1><<<dim3(6, 128, 1), 256>>>(att, dr_wih, dr_bih, xg_dr,
                                           768, 512, 0, 0, 0, 1, 1);

    // phase C: persistent reasoning GRUs — sr (128 seqs, T=256) || dr (128 seqs, T=128)
    {
        GG ga; ga.xg = xg_sr; ga.whh = sr_whh; ga.bhh = sr_bhh;
        ga.h0 = hsr0; ga.h1 = hsr1; ga.ys = nullptr; ga.hmax = srmax;
        ga.T = 256; ga.nsg = 8;
        GG gb; gb.xg = xg_dr; gb.whh = dr_whh; gb.bhh = dr_bhh;
        gb.h0 = hdr0; gb.h1 = hdr1; gb.ys = nullptr; gb.hmax = drmax;
        gb.T = 128; gb.nsg = 8;
        gru_phase<<<128, 128, GRU_SMEM>>>(ga, gb);  // 128 blocks <= 148 SMs, 1/SM
    }

    final_kernel<<<1, 512>>>(gate_w, gate_b, out_w, out_b, out);
}

// round 7
// speedup vs baseline: 2.4186x; 1.5730x over previous
#include <cuda_runtime.h>
#include <math.h>

// Problem dims: B=4 O=4 L=128 N=8 V=256 H=256, Ls=2L=256, BO=16, BON=128, NL=1024

// ---------------- scratch (device globals; no allocation allowed) ----------------
__device__ float g_stmt_in[16 * 256 * 256];
__device__ float g_xg_stmt[16 * 256 * 768];
__device__ float g_stmt_h[16 * 256 * 256];
__device__ float g_xg_docs[128 * 128 * 768];
__device__ float g_docs_h[128 * 128 * 256];
__device__ float g_hs0[16 * 256], g_hs1[16 * 256];
__device__ float g_hd0[128 * 256], g_hd1[128 * 256];
__device__ float g_match[128 * 256 * 128];
__device__ float g_p1[128 * 256 * 128];
__device__ float g_p2t[128 * 128 * 256];
__device__ float g_read_sum[128 * 256 * 256];
__device__ float g_doc_read[128 * 128 * 256];
__device__ float g_dri[128 * 128 * 512];
__device__ float g_mm[16 * 1024 * 1024];
__device__ float g_att[128 * 128 * 512];
__device__ float g_xg_sr[128 * 256 * 768];
__device__ float g_xg_dr[128 * 128 * 768];
__device__ float g_hsr0[128 * 256], g_hsr1[128 * 256];
__device__ float g_hdr0[128 * 256], g_hdr1[128 * 256];
__device__ float g_srmax[128 * 256], g_drmax[128 * 256];

// slotted group barriers: 32 slots, 128B stride
__device__ unsigned g_bcnt[32 * 32];
__device__ unsigned g_bgen[32 * 32];

// ---------------- init ----------------
__global__ void init_state() {
    int i = blockIdx.x * 256 + threadIdx.x;  // 32768 threads
    if (i < 32 * 32) { g_bcnt[i] = 0u; g_bgen[i] = 0u; }
    if (i < 16 * 256) { g_hs0[i] = 0.f; g_hs1[i] = 0.f; }
    if (i < 128 * 256) {
        g_hd0[i] = 0.f;  g_hd1[i] = 0.f;
        g_hsr0[i] = 0.f; g_hsr1[i] = 0.f;
        g_hdr0[i] = 0.f; g_hdr1[i] = 0.f;
    }
}

// ---------------- build stmt = cat(question, answer) ----------------
__global__ void concat_stmt(const float* __restrict__ statement,
                            const float* __restrict__ answer) {
    int idx = blockIdx.x * 256 + threadIdx.x;  // 1048576
    int v = idx & 255;
    int s = (idx >> 8) & 255;
    int bo = idx >> 16;
    int b = bo >> 2;
    float val;
    if (s < 128) val = statement[(b * 128 + s) * 256 + v];
    else         val = answer[(bo * 128 + (s - 128)) * 256 + v];
    g_stmt_in[idx] = val;
}

// ---------------- dri = cat(docs, doc_read) ----------------
__global__ void concat_dri() {
    for (int idx = blockIdx.x * blockDim.x + threadIdx.x; idx < 128 * 128 * 512;
         idx += gridDim.x * blockDim.x) {
        int h = idx & 511;
        int rest = idx >> 9;
        g_dri[idx] = (h < 256) ? g_docs_h[rest * 256 + h]
                               : g_doc_read[rest * 256 + (h - 256)];
    }
}

// ---------------- tf32 tensor-core GEMM ----------------
__device__ __forceinline__ unsigned f2tf(float x) {
    unsigned r;
    asm("cvt.rna.tf32.f32 %0, %1;" : "=r"(r) : "f"(x));
    return r;
}

__device__ __forceinline__ void mma_tf32(float4& d, const unsigned* a, const unsigned* b) {
    asm volatile(
        "mma.sync.aligned.m16n8k8.row.col.f32.tf32.tf32.f32 "
        "{%0,%1,%2,%3}, {%4,%5,%6,%7}, {%8,%9}, {%0,%1,%2,%3};"
        : "+f"(d.x), "+f"(d.y), "+f"(d.z), "+f"(d.w)
        : "r"(a[0]), "r"(a[1]), "r"(a[2]), "r"(a[3]), "r"(b[0]), "r"(b[1]));
}

// Tile 128x128, K-tile 32, 256 threads (8 warps, each 64x32).
// TB=1: C = A[M,K] * B[N,K]^T (+bias);  TB=0: C = A[M,K] * B[K,N] (+bias)
template <int TB>
__global__ void __launch_bounds__(256) gemm_tf32(
    const float* __restrict__ A, const float* __restrict__ B,
    const float* __restrict__ bias, float* __restrict__ C,
    int N, int K, long long sA, long long sB, long long sC,
    int divA, int divB) {
    const int tid = threadIdx.x;
    int z = blockIdx.z;
    A += (long long)(z / divA) * sA + (long long)(blockIdx.y * 128) * K;
    if (TB) B += (long long)(z / divB) * sB + (long long)(blockIdx.x * 128) * K;
    else    B += (long long)(z / divB) * sB + blockIdx.x * 128;
    C += (long long)z * sC + (long long)(blockIdx.y * 128) * N + blockIdx.x * 128;

    __shared__ unsigned As[128 * 36];   // [m][k], pitch 36 -> conflict-free frags
    __shared__ unsigned Bs[128 * 36];   // TN: [n][k] pitch 36; NN: [k][n] pitch 132

    const int warp = tid >> 5, lane = tid & 31;
    const int wm = (warp & 1) * 64, wn = (warp >> 1) * 32;
    const int lq = lane >> 2, lr = lane & 3;

    const int sm = tid >> 3;         // 0..31 (row group, +32*i)
    const int sk = (tid & 7) * 4;    // 0..28
    const int bk = tid >> 5;         // 0..7 (NN k row, +8*i)
    const int bn = (tid & 31) * 4;   // 0..124

    float4 acc[4][4];
#pragma unroll
    for (int i = 0; i < 4; i++)
#pragma unroll
        for (int j = 0; j < 4; j++) acc[i][j] = make_float4(0.f, 0.f, 0.f, 0.f);

    float4 pa[4], pb[4];
#pragma unroll
    for (int i = 0; i < 4; i++)
        pa[i] = *reinterpret_cast<const float4*>(&A[(long long)(sm + 32 * i) * K + sk]);
    if (TB) {
#pragma unroll
        for (int i = 0; i < 4; i++)
            pb[i] = *reinterpret_cast<const float4*>(&B[(long long)(sm + 32 * i) * K + sk]);
    } else {
#pragma unroll
        for (int i = 0; i < 4; i++)
            pb[i] = *reinterpret_cast<const float4*>(&B[(long long)(bk + 8 * i) * N + bn]);
    }

    int k0 = 0;
    for (;;) {
#pragma unroll
        for (int i = 0; i < 4; i++) {
            uint4 u;
            u.x = f2tf(pa[i].x); u.y = f2tf(pa[i].y); u.z = f2tf(pa[i].z); u.w = f2tf(pa[i].w);
            *reinterpret_cast<uint4*>(&As[(sm + 32 * i) * 36 + sk]) = u;
        }
#pragma unroll
        for (int i = 0; i < 4; i++) {
            uint4 u;
            u.x = f2tf(pb[i].x); u.y = f2tf(pb[i].y); u.z = f2tf(pb[i].z); u.w = f2tf(pb[i].w);
            if (TB) *reinterpret_cast<uint4*>(&Bs[(sm + 32 * i) * 36 + sk]) = u;
            else    *reinterpret_cast<uint4*>(&Bs[(bk + 8 * i) * 132 + bn]) = u;
        }
        __syncthreads();

        int k1 = k0 + 32;
        if (k1 < K) {
#pragma unroll
            for (int i = 0; i < 4; i++)
                pa[i] = *reinterpret_cast<const float4*>(&A[(long long)(sm + 32 * i) * K + k1 + sk]);
            if (TB) {
#pragma unroll
                for (int i = 0; i < 4; i++)
                    pb[i] = *reinterpret_cast<const float4*>(&B[(long long)(sm + 32 * i) * K + k1 + sk]);
            } else {
#pragma unroll
                for (int i = 0; i < 4; i++)
                    pb[i] = *reinterpret_cast<const float4*>(&B[(long long)(k1 + bk + 8 * i) * N + bn]);
            }
        }

#pragma unroll
        for (int kk = 0; kk < 32; kk += 8) {
            unsigned a[4][4];
#pragma unroll
            for (int mt = 0; mt < 4; mt++) {
                int r = (wm + mt * 16 + lq) * 36 + kk + lr;
                a[mt][0] = As[r];
                a[mt][1] = As[r + 8 * 36];
                a[mt][2] = As[r + 4];
                a[mt][3] = As[r + 8 * 36 + 4];
            }
            unsigned b[4][2];
#pragma unroll
            for (int nt = 0; nt < 4; nt++) {
                if (TB) {
                    int r = (wn + nt * 8 + lq) * 36 + kk + lr;
                    b[nt][0] = Bs[r];
                    b[nt][1] = Bs[r + 4];
                } else {
                    int r = (kk + lr) * 132 + wn + nt * 8 + lq;
                    b[nt][0] = Bs[r];
                    b[nt][1] = Bs[r + 4 * 132];
                }
            }
#pragma unroll
            for (int mt = 0; mt < 4; mt++)
#pragma unroll
                for (int nt = 0; nt < 4; nt++) mma_tf32(acc[mt][nt], a[mt], b[nt]);
        }
        if (k1 >= K) break;
        __syncthreads();
        k0 = k1;
    }

#pragma unroll
    for (int nt = 0; nt < 4; nt++) {
        int col = wn + nt * 8 + 2 * lr;
        float bx = 0.f, by = 0.f;
        if (bias) {
            int cg = blockIdx.x * 128 + col;
            bx = bias[cg]; by = bias[cg + 1];
        }
#pragma unroll
        for (int mt = 0; mt < 4; mt++) {
            int row = wm + mt * 16 + lq;
            float4 v = acc[mt][nt];
            float2 v0 = make_float2(v.x + bx, v.y + by);
            float2 v1 = make_float2(v.z + bx, v.w + by);
            *reinterpret_cast<float2*>(&C[(long long)row * N + col]) = v0;
            *reinterpret_cast<float2*>(&C[(long long)(row + 8) * N + col]) = v1;
        }
    }
}

// ---------------- softmax: 1024 cols, block per row, regs-resident ----------------
__global__ void __launch_bounds__(256) softmax_block1024(const float* __restrict__ in,
                                                         float* __restrict__ out) {
    long long row = blockIdx.x;
    const float4* x = reinterpret_cast<const float4*>(in + row * 1024);
    float4* y = reinterpret_cast<float4*>(out + row * 1024);
    int tid = threadIdx.x, warp = tid >> 5, lane = tid & 31;
    __shared__ float redm[8], reds[8];
    float4 v = x[tid];
    float m = fmaxf(fmaxf(v.x, v.y), fmaxf(v.z, v.w));
#pragma unroll
    for (int off = 16; off; off >>= 1) m = fmaxf(m, __shfl_xor_sync(0xffffffffu, m, off));
    if (lane == 0) redm[warp] = m;
    __syncthreads();
    m = redm[0];
#pragma unroll
    for (int i = 1; i < 8; i++) m = fmaxf(m, redm[i]);
    v.x = expf(v.x - m); v.y = expf(v.y - m); v.z = expf(v.z - m); v.w = expf(v.w - m);
    float s = v.x + v.y + v.z + v.w;
#pragma unroll
    for (int off = 16; off; off >>= 1) s += __shfl_xor_sync(0xffffffffu, s, off);
    if (lane == 0) reds[warp] = s;
    __syncthreads();
    s = reds[0];
#pragma unroll
    for (int i = 1; i < 8; i++) s += reds[i];
    float inv = 1.f / s;
    v.x *= inv; v.y *= inv; v.z *= inv; v.w *= inv;
    y[tid] = v;
}

// ---------------- softmax: 128 cols, warp per row (8 rows per block) ----------------
__global__ void __launch_bounds__(256) softmax_warp128(const float* __restrict__ in,
                                                       float* __restrict__ out) {
    int warp = threadIdx.x >> 5, lane = threadIdx.x & 31;
    long long row = (long long)blockIdx.x * 8 + warp;
    const float4* x = reinterpret_cast<const float4*>(in + row * 128);
    float4* y = reinterpret_cast<float4*>(out + row * 128);
    float4 v = x[lane];
    float m = fmaxf(fmaxf(v.x, v.y), fmaxf(v.z, v.w));
#pragma unroll
    for (int off = 16; off; off >>= 1) m = fmaxf(m, __shfl_xor_sync(0xffffffffu, m, off));
    v.x = expf(v.x - m); v.y = expf(v.y - m); v.z = expf(v.z - m); v.w = expf(v.w - m);
    float s = v.x + v.y + v.z + v.w;
#pragma unroll
    for (int off = 16; off; off >>= 1) s += __shfl_xor_sync(0xffffffffu, s, off);
    float inv = 1.f / s;
    v.x *= inv; v.y *= inv; v.z *= inv; v.w *= inv;
    y[lane] = v;
}

// ---------------- column softmax of match over s, output transposed [bon][l][s] ----------------
__global__ void __launch_bounds__(128) softmax_cols_t() {
    int bon = blockIdx.y;
    int l = blockIdx.x * 4 + (threadIdx.x >> 5);
    int lane = threadIdx.x & 31;
    const float* base = g_match + (long long)bon * 256 * 128 + l;
    float v[8];
    float m = -1e30f;
#pragma unroll
    for (int i = 0; i < 8; i++) {
        v[i] = base[(lane + 32 * i) * 128];
        m = fmaxf(m, v[i]);
    }
#pragma unroll
    for (int off = 16; off; off >>= 1) m = fmaxf(m, __shfl_xor_sync(0xffffffffu, m, off));
    float sum = 0.f;
#pragma unroll
    for (int i = 0; i < 8; i++) { v[i] = expf(v[i] - m); sum += v[i]; }
#pragma unroll
    for (int off = 16; off; off >>= 1) sum += __shfl_xor_sync(0xffffffffu, sum, off);
    float inv = 1.f / sum;
    float* o = g_p2t + ((long long)bon * 128 + l) * 256;
#pragma unroll
    for (int i = 0; i < 8; i++) o[lane + 32 * i] = v[i] * inv;
}

// ---------------- 8-block group barrier (blocks of one sgrp share a slot) -------
__device__ __forceinline__ void group_barrier(int slot) {
    __syncthreads();
    if (threadIdx.x == 0) {
        unsigned* cnt = &g_bcnt[slot * 32];
        volatile unsigned* gen = (volatile unsigned*)&g_bgen[slot * 32];
        unsigned g0 = *gen;
        __threadfence();
        if (atomicAdd(cnt, 1u) == 7u) {
            *cnt = 0u;
            __threadfence();
            *gen = g0 + 1u;
        } else {
            while (*gen == g0) {}
            __threadfence();
        }
    }
    __syncthreads();
}

// ---------------- persistent fused GRU phase ----------------
struct GG {
    const float* xg;    // [nseq][T][768]
    const float* whh;   // [768][256]
    const float* bhh;   // [768]
    float* h0;          // [nseq][256] (t even input)
    float* h1;
    float* ys;          // optional [nseq][T][256]
    float* hmax;        // optional [nseq][256]
    int T;
    int nsg;            // seq groups of 16
    int slotbase;       // barrier slot base (one slot per sgrp)
};

#define WP 260  // padded weight row pitch (floats)

// packed fp32x2 FMA (sm_10x): acc{lo,hi} += a{lo,hi} * b{lo,hi}
#define FMA2(acc, a, b) \
    asm("fma.rn.f32x2 %0, %1, %2, %0;" : "+l"(acc) : "l"(a), "l"(b))
#define UNPK(lo, hi, v) \
    asm("mov.b64 {%0,%1}, %2;" : "=f"(lo), "=f"(hi) : "l"(v))

__device__ __forceinline__ float red2(unsigned long long a, unsigned long long b) {
    float l0, h0, l1, h1;
    UNPK(l0, h0, a); UNPK(l1, h1, b);
    return (l0 + h0) + (l1 + h1);
}

// block = 128 threads, tile = 16 seqs x 32 cols. grid = (ga.nsg + gb.nsg) * 8 blocks.
// Blocks of the same sgrp sync among themselves only (8-block barrier) and exit at T.
__global__ void __launch_bounds__(128) gru_phase(GG ga, GG gb) {
    extern __shared__ float sm[];
    float* ws = sm;               // 96 x WP
    float* hs = sm + 96 * WP;     // 16 x 256

    GG g;
    int sgrp, colbase;
    {
        int b = blockIdx.x;
        int blocks0 = ga.nsg * 8;
        if (b < blocks0) { g = ga; sgrp = b >> 3; colbase = (b & 7) * 32; }
        else { g = gb; int bb = b - blocks0; sgrp = bb >> 3; colbase = (bb & 7) * 32; }
    }
    const int slot = g.slotbase + sgrp;
    const int tid = threadIdx.x;
    const int ci = tid & 15;
    const int sj = tid >> 4;  // 0..7

    // load weight slice: rows {gate*256 + colbase + j}, j in [0,32), all 256 k
    for (int i = tid; i < 96 * 64; i += 128) {
        int r = i >> 6, q = i & 63;
        float4 v = __ldg(reinterpret_cast<const float4*>(
            &g.whh[(long long)((r >> 5) * 256 + colbase + (r & 31)) * 256 + q * 4]));
        *reinterpret_cast<float4*>(&ws[r * WP + q * 4]) = v;
    }
    const int c0 = colbase + ci, c1 = c0 + 16;
    const float br0 = g.bhh[c0], bz0 = g.bhh[256 + c0], bn0 = g.bhh[512 + c0];
    const float br1 = g.bhh[c1], bz1 = g.bhh[256 + c1], bn1 = g.bhh[512 + c1];
    float mx00 = -1e30f, mx01 = -1e30f, mx10 = -1e30f, mx11 = -1e30f;

    // weight rows as packed-pair pointers: [R c0][R c1][Z c0][Z c1][N c0][N c1]
    const ulonglong2* wp[6];
    wp[0] = reinterpret_cast<const ulonglong2*>(&ws[(0 * 32 + ci) * WP]);
    wp[1] = reinterpret_cast<const ulonglong2*>(&ws[(0 * 32 + ci + 16) * WP]);
    wp[2] = reinterpret_cast<const ulonglong2*>(&ws[(1 * 32 + ci) * WP]);
    wp[3] = reinterpret_cast<const ulonglong2*>(&ws[(1 * 32 + ci + 16) * WP]);
    wp[4] = reinterpret_cast<const ulonglong2*>(&ws[(2 * 32 + ci) * WP]);
    wp[5] = reinterpret_cast<const ulonglong2*>(&ws[(2 * 32 + ci + 16) * WP]);
    const ulonglong2* h0p = reinterpret_cast<const ulonglong2*>(&hs[sj * 256]);
    const ulonglong2* h1p = reinterpret_cast<const ulonglong2*>(&hs[(sj + 8) * 256]);

    const int T = g.T;
    for (int t = 0; t < T; t++) {
        const float* hin = (t & 1) ? g.h1 : g.h0;
        float* hout = (t & 1) ? g.h0 : g.h1;
        const float* tilebase = hin + (long long)sgrp * 16 * 256;
        // stage h tile [16][256] (L2-only loads: written by other SMs last step)
#pragma unroll
        for (int i = 0; i < 8; i++) {
            int idx = tid + i * 128;  // 0..1023 float4
            float4 v = __ldcg(reinterpret_cast<const float4*>(tilebase) + idx);
            *reinterpret_cast<float4*>(&hs[idx * 4]) = v;
        }
        // prefetch xg for this thread's 4 cells
        const long long base0 = ((long long)(sgrp * 16 + sj) * T + t) * 768;
        const long long base1 = ((long long)(sgrp * 16 + sj + 8) * T + t) * 768;
        float xr00 = __ldg(&g.xg[base0 + c0]);
        float xz00 = __ldg(&g.xg[base0 + 256 + c0]);
        float xn00 = __ldg(&g.xg[base0 + 512 + c0]);
        float xr01 = __ldg(&g.xg[base0 + c1]);
        float xz01 = __ldg(&g.xg[base0 + 256 + c1]);
        float xn01 = __ldg(&g.xg[base0 + 512 + c1]);
        float xr10 = __ldg(&g.xg[base1 + c0]);
        float xz10 = __ldg(&g.xg[base1 + 256 + c0]);
        float xn10 = __ldg(&g.xg[base1 + 512 + c0]);
        float xr11 = __ldg(&g.xg[base1 + c1]);
        float xz11 = __ldg(&g.xg[base1 + 256 + c1]);
        float xn11 = __ldg(&g.xg[base1 + 512 + c1]);
        __syncthreads();

        // acc[wrow][seq][parity], f32x2-packed (even-k lane, odd-k lane)
        unsigned long long acc[6][2][2];
#pragma unroll
        for (int i = 0; i < 6; i++)
#pragma unroll
            for (int s = 0; s < 2; s++) { acc[i][s][0] = 0ull; acc[i][s][1] = 0ull; }

#pragma unroll 4
        for (int q = 0; q < 64; q++) {
            ulonglong2 h0 = h0p[q];
            ulonglong2 h1 = h1p[q];
#pragma unroll
            for (int i = 0; i < 6; i++) {
                ulonglong2 w = wp[i][q];
                FMA2(acc[i][0][0], w.x, h0.x); FMA2(acc[i][0][1], w.y, h0.y);
                FMA2(acc[i][1][0], w.x, h1.x); FMA2(acc[i][1][1], w.y, h1.y);
            }
        }
        float aR00 = red2(acc[0][0][0], acc[0][0][1]);
        float aR10 = red2(acc[0][1][0], acc[0][1][1]);
        float aR01 = red2(acc[1][0][0], acc[1][0][1]);
        float aR11 = red2(acc[1][1][0], acc[1][1][1]);
        float aZ00 = red2(acc[2][0][0], acc[2][0][1]);
        float aZ10 = red2(acc[2][1][0], acc[2][1][1]);
        float aZ01 = red2(acc[3][0][0], acc[3][0][1]);
        float aZ11 = red2(acc[3][1][0], acc[3][1][1]);
        float aN00 = red2(acc[4][0][0], acc[4][0][1]);
        float aN10 = red2(acc[4][1][0], acc[4][1][1]);
        float aN01 = red2(acc[5][0][0], acc[5][0][1]);
        float aN11 = red2(acc[5][1][0], acc[5][1][1]);

        // gate math + stores (cells: [seq-half s][col-half c])
#pragma unroll
        for (int s = 0; s < 2; s++) {
            int sl = sj + 8 * s;
            long long seq = sgrp * 16 + sl;
#pragma unroll
            for (int c = 0; c < 2; c++) {
                int col = colbase + ci + 16 * c;
                float aR = s ? (c ? aR11 : aR10) : (c ? aR01 : aR00);
                float aZ = s ? (c ? aZ11 : aZ10) : (c ? aZ01 : aZ00);
                float aN = s ? (c ? aN11 : aN10) : (c ? aN01 : aN00);
                float xr = s ? (c ? xr11 : xr10) : (c ? xr01 : xr00);
                float xz = s ? (c ? xz11 : xz10) : (c ? xz01 : xz00);
                float xn = s ? (c ? xn11 : xn10) : (c ? xn01 : xn00);
                float hr = aR + (c ? br1 : br0);
                float hz = aZ + (c ? bz1 : bz0);
                float hn = aN + (c ? bn1 : bn0);
                float r = 1.f / (1.f + expf(-(xr + hr)));
                float z = 1.f / (1.f + expf(-(xz + hz)));
                float n = tanhf(xn + r * hn);
                float hold = hs[sl * 256 + col];
                float h = (1.f - z) * n + z * hold;
                hout[seq * 256 + col] = h;
                if (g.ys) g.ys[(seq * T + t) * 256 + col] = h;
                if (s) { if (c) mx11 = fmaxf(mx11, h); else mx10 = fmaxf(mx10, h); }
                else   { if (c) mx01 = fmaxf(mx01, h); else mx00 = fmaxf(mx00, h); }
            }
        }
        if (t + 1 < T) group_barrier(slot);
    }
    if (g.hmax) {
        long long s0 = sgrp * 16 + sj, s1 = s0 + 8;
        g.hmax[s0 * 256 + c0] = mx00;
        g.hmax[s0 * 256 + c1] = mx01;
        g.hmax[s1 * 256 + c0] = mx10;
        g.hmax[s1 * 256 + c1] = mx11;
    }
}

// ---------------- final: coef gate, feat, output head, softmax over options ----------------
__global__ void __launch_bounds__(512) final_kernel(
    const float* __restrict__ gate_w, const float* __restrict__ gate_b,
    const float* __restrict__ out_w, const float* __restrict__ out_b,
    float* __restrict__ out) {
    __shared__ float coef[128];
    __shared__ float logits[16];
    int tid = threadIdx.x, w = tid >> 5, lane = tid & 31;
    for (int bon = w; bon < 128; bon += 16) {
        float s = 0.f;
        for (int d = lane; d < 512; d += 32) {
            float rv = (d < 256) ? g_srmax[bon * 256 + d] : g_drmax[bon * 256 + d - 256];
            s += rv * gate_w[d];
        }
#pragma unroll
        for (int off = 16; off; off >>= 1) s += __shfl_xor_sync(0xffffffffu, s, off);
        if (lane == 0) coef[bon] = s + gate_b[0];
    }
    __syncthreads();
    {
        int bo = w;
        float acc = 0.f;
        for (int d = lane; d < 1024; d += 32) {
            float v;
            if (d < 512) {
                float mxv = -1e30f;
#pragma unroll
                for (int n = 0; n < 8; n++) {
                    int bon = bo * 8 + n;
                    float rv = (d < 256) ? g_srmax[bon * 256 + d] : g_drmax[bon * 256 + d - 256];
                    mxv = fmaxf(mxv, coef[bon] * rv);
                }
                v = mxv;
            } else {
                int dd = d - 512;
                float smv = 0.f;
#pragma unroll
                for (int n = 0; n < 8; n++) {
                    int bon = bo * 8 + n;
                    float rv = (dd < 256) ? g_srmax[bon * 256 + dd] : g_drmax[bon * 256 + dd - 256];
                    smv += coef[bon] * rv;
                }
                v = smv * 0.125f;
            }
            acc += v * out_w[d];
        }
#pragma unroll
        for (int off = 16; off; off >>= 1) acc += __shfl_xor_sync(0xffffffffu, acc, off);
        if (lane == 0) logits[bo] = acc + out_b[0];
    }
    __syncthreads();
    if (tid < 4) {
        int b = tid;
        float m = -1e30f;
        for (int o = 0; o < 4; o++) m = fmaxf(m, logits[b * 4 + o]);
        float e[4], s = 0.f;
        for (int o = 0; o < 4; o++) { e[o] = expf(logits[b * 4 + o] - m); s += e[o]; }
        for (int o = 0; o < 4; o++) out[b * 4 + o] = e[o] / s;
    }
}

// ---------------- host orchestration ----------------
#define SYM(p, s) do { void* _t = nullptr; cudaGetSymbolAddress(&_t, s); p = (float*)_t; } while (0)

static const int GRU_SMEM = (96 * WP + 16 * 256) * 4;  // 116,224 B

extern "C" void kernel_launch(void* const* d_in, const int* in_sizes, int n_in,
                              void* d_out, int out_size) {
    const float* statement = (const float*)d_in[0];
    const float* answer    = (const float*)d_in[1];
    const float* refs      = (const float*)d_in[2];
    const float* ctx_wih   = (const float*)d_in[3];
    const float* ctx_whh   = (const float*)d_in[4];
    const float* ctx_bih   = (const float*)d_in[5];
    const float* ctx_bhh   = (const float*)d_in[6];
    const float* sr_wih    = (const float*)d_in[7];
    const float* sr_whh    = (const float*)d_in[8];
    const float* sr_bih    = (const float*)d_in[9];
    const float* sr_bhh    = (const float*)d_in[10];
    const float* dr_wih    = (const float*)d_in[11];
    const float* dr_whh    = (const float*)d_in[12];
    const float* dr_bih    = (const float*)d_in[13];
    const float* dr_bhh    = (const float*)d_in[14];
    const float* gate_w    = (const float*)d_in[15];
    const float* gate_b    = (const float*)d_in[16];
    const float* out_w     = (const float*)d_in[17];
    const float* out_b     = (const float*)d_in[18];
    float* out = (float*)d_out;

    float *stmt_in, *xg_stmt, *stmt_h, *xg_docs, *docs_h;
    float *hs0, *hs1, *hd0, *hd1;
    float *matchb, *p1, *p2t, *read_sum, *doc_read, *dri, *mmb, *att;
    float *xg_sr, *xg_dr, *hsr0, *hsr1, *hdr0, *hdr1, *srmax, *drmax;
    SYM(stmt_in, g_stmt_in); SYM(xg_stmt, g_xg_stmt); SYM(stmt_h, g_stmt_h);
    SYM(xg_docs, g_xg_docs); SYM(docs_h, g_docs_h);
    SYM(hs0, g_hs0); SYM(hs1, g_hs1); SYM(hd0, g_hd0); SYM(hd1, g_hd1);
    SYM(matchb, g_match); SYM(p1, g_p1); SYM(p2t, g_p2t);
    SYM(read_sum, g_read_sum); SYM(doc_read, g_doc_read); SYM(dri, g_dri);
    SYM(mmb, g_mm); SYM(att, g_att);
    SYM(xg_sr, g_xg_sr); SYM(xg_dr, g_xg_dr);
    SYM(hsr0, g_hsr0); SYM(hsr1, g_hsr1); SYM(hdr0, g_hdr0); SYM(hdr1, g_hdr1);
    SYM(srmax, g_srmax); SYM(drmax, g_drmax);

    cudaFuncSetAttribute(gru_phase, cudaFuncAttributeMaxDynamicSharedMemorySize, GRU_SMEM);

    init_state<<<128, 256>>>();
    concat_stmt<<<4096, 256>>>(statement, answer);

    // input projections for ctx GRU (TN: W is [768, in])
    gemm_tf32<1><<<dim3(6, 32, 1), 256>>>(stmt_in, ctx_wih, ctx_bih, xg_stmt,
                                          768, 256, 0, 0, 0, 1, 1);
    gemm_tf32<1><<<dim3(6, 128, 1), 256>>>(refs, ctx_wih, ctx_bih, xg_docs,
                                           768, 256, 0, 0, 0, 1, 1);

    // phase A: persistent ctx GRU — stmt (16 seqs, T=256) || docs (128 seqs, T=128)
    {
        GG gs; gs.xg = xg_stmt; gs.whh = ctx_whh; gs.bhh = ctx_bhh;
        gs.h0 = hs0; gs.h1 = hs1; gs.ys = stmt_h; gs.hmax = nullptr;
        gs.T = 256; gs.nsg = 1; gs.slotbase = 0;
        GG gd; gd.xg = xg_docs; gd.whh = ctx_whh; gd.bhh = ctx_bhh;
        gd.h0 = hd0; gd.h1 = hd1; gd.ys = docs_h; gd.hmax = nullptr;
        gd.T = 128; gd.nsg = 8; gd.slotbase = 16;
        gru_phase<<<72, 128, GRU_SMEM>>>(gs, gd);  // 72 blocks, 1/SM
    }

    // match[bon][s][l] = stmt[bo,s,:] . docs[bon,l,:]
    gemm_tf32<1><<<dim3(1, 2, 128), 256>>>(stmt_h, docs_h, nullptr, matchb,
                                           128, 256, 65536, 32768, 32768, 8, 1);
    softmax_warp128<<<4096, 256>>>(matchb, p1);
    softmax_cols_t<<<dim3(32, 128), 128>>>();
    // read_sum = p1 @ docs ; doc_read = p2t @ stmt
    gemm_tf32<0><<<dim3(2, 2, 128), 256>>>(p1, docs_h, nullptr, read_sum,
                                           256, 128, 32768, 32768, 65536, 1, 1);
    gemm_tf32<0><<<dim3(2, 1, 128), 256>>>(p2t, stmt_h, nullptr, doc_read,
                                           256, 256, 32768, 65536, 32768, 1, 8);
    concat_dri<<<4096, 256>>>();

    // doc-doc cross attention per bo: mm = dri @ dri^T ; softmax ; att = p3 @ dri
    gemm_tf32<1><<<dim3(8, 8, 16), 256>>>(dri, dri, nullptr, mmb,
                                          1024, 512, 524288, 524288, 1048576, 1, 1);
    softmax_block1024<<<16384, 256>>>(mmb, mmb);
    gemm_tf32<0><<<dim3(4, 8, 16), 256>>>(mmb, dri, nullptr, att,
                                          512, 1024, 1048576, 524288, 524288, 1, 1);

    // input projections for reasoning GRUs
    gemm_tf32<1><<<dim3(6, 256, 1), 256>>>(read_sum, sr_wih, sr_bih, xg_sr,
                                           768, 256, 0, 0, 0, 1, 1);
    gemm_tf32<1><<<dim3(6, 128, 1), 256>>>(att, dr_wih, dr_bih, xg_dr,
                                           768, 512, 0, 0, 0, 1, 1);

    // phase C: persistent reasoning GRUs — sr (128 seqs, T=256) || dr (128 seqs, T=128)
    {
        GG ga; ga.xg = xg_sr; ga.whh = sr_whh; ga.bhh = sr_bhh;
        ga.h0 = hsr0; ga.h1 = hsr1; ga.ys = nullptr; ga.hmax = srmax;
        ga.T = 256; ga.nsg = 8; ga.slotbase = 0;
        GG gb; gb.xg = xg_dr; gb.whh = dr_whh; gb.bhh = dr_bhh;
        gb.h0 = hdr0; gb.h1 = hdr1; gb.ys = nullptr; gb.hmax = drmax;
        gb.T = 128; gb.nsg = 8; gb.slotbase = 16;
        gru_phase<<<128, 128, GRU_SMEM>>>(ga, gb);  // 128 blocks, 1/SM
    }

    final_kernel<<<1, 512>>>(gate_w, gate_b, out_w, out_b, out);
}